// round 3
// baseline (speedup 1.0000x reference)
#include <cuda_runtime.h>
#include <math.h>

#define NG 16
#define GS 16384   // 128*128 block stride
#define CLU 8

// ---------------- device scratch ----------------
__device__ float g_A [NG*GS];
__device__ float g_h [NG*GS];
__device__ float g_hb[NG*GS];
__device__ float g_x2[NG*GS];
__device__ float g_S [NG*GS];
__device__ float g_T [NG*GS];
__device__ float g_wt[12*GS];
__device__ float g_w1t[640*128];
__device__ float g_xs[NG*5*128];
__device__ float g_fit[NG*128];
__device__ float g_ax[NG*128];
__device__ float g_aq[NG*128];
__device__ int   g_perm[NG*128];

#define CLUSTER_SYNC() do{ \
  asm volatile("barrier.cluster.arrive.aligned;" ::: "memory"); \
  asm volatile("barrier.cluster.wait.aligned;"   ::: "memory"); }while(0)

__device__ __forceinline__ void fma8(float a, const float* b, float acc[8]){
  float4 b0 = *(const float4*)b;
  float4 b1 = *(const float4*)(b+4);
  acc[0]=fmaf(a,b0.x,acc[0]); acc[1]=fmaf(a,b0.y,acc[1]);
  acc[2]=fmaf(a,b0.z,acc[2]); acc[3]=fmaf(a,b0.w,acc[3]);
  acc[4]=fmaf(a,b1.x,acc[4]); acc[5]=fmaf(a,b1.y,acc[5]);
  acc[6]=fmaf(a,b1.z,acc[6]); acc[7]=fmaf(a,b1.w,acc[7]);
}

// smem carve (floats):
// 0     sH     16384
// 16384 sW     16384
// 32768 sAc     2048
// 34816 sAgg    2176   (also sS / sAt / sSa / sQt)
// 36992 sHt     2176   (also sQr)
// 39168 sDeg      16
// 39184 sax      128
// 39312 sInv      16
// 39328 sa       128
// 39456 sb       128
// 39584 sfit     128
// 39712 sperm    128 (int)
#define SMF 39840

// ---------------- prep: weight transposes ----------------
__global__ void k_prep(const float* __restrict__ c0r, const float* __restrict__ c0t,
                       const float* __restrict__ cwr, const float* __restrict__ cwt,
                       const float* __restrict__ plw, const float* __restrict__ w1){
  int idx = blockIdx.x*256 + threadIdx.x;
  if (idx < 12*GS){
    int slot = idx >> 14, e = idx & 16383;
    int c = e >> 7, o = e & 127;
    const float* src; int Cin;
    if (slot == 0){ src = c0r; Cin = 64; }
    else if (slot == 1){ src = c0t; Cin = 64; }
    else if (slot < 6){ src = cwr + (slot-2)*GS; Cin = 128; }
    else if (slot < 10){ src = cwt + (slot-6)*GS; Cin = 128; }
    else { src = plw + (slot-10)*GS; Cin = 128; }
    g_wt[idx] = (c < Cin) ? src[o*Cin + c] : 0.f;
  } else if (idx < 12*GS + 640*128){
    int j = idx - 12*GS;
    int c = j >> 7, o = j & 127;
    g_w1t[j] = w1[o*640 + c];
  }
}

// ---------------- stage device functions ----------------
__device__ void dv_conv(float* sm, int g, int r, int tid,
                        const float* __restrict__ X, int ld_in,
                        float* __restrict__ houtg,
                        const float* __restrict__ wtrel, const float* __restrict__ wtroot,
                        const float* __restrict__ brel, int slot, int n, int Cin, float invn)
{
  float* sH  = sm;
  float* sW  = sm + 16384;
  float* sAc = sm + 32768;
  float* sAgg= sm + 34816;
  float* sHt = sm + 36992;
  float* sDeg= sm + 39168;
  int j0 = r*16;
  if (j0 >= n) return;

  if (Cin == 128){
    const float4* s4 = (const float4*)X;
    float4* d4 = (float4*)sH;
    for (int i4 = tid; i4 < n*32; i4 += 256) d4[i4] = s4[i4];
  } else {
    for (int idx = tid; idx < n*128; idx += 256){
      int i = idx >> 7, c = idx & 127;
      sH[idx] = (c < Cin) ? X[i*ld_in + c] : 0.f;
    }
  }
  for (int idx = tid; idx < n*16; idx += 256){
    int i = idx >> 4, jt = idx & 15;
    int j = j0 + jt;
    sAc[idx] = (j < n) ? g_A[g*GS + i*128 + j] : 0.f;
  }
  __syncthreads();
  if (tid < 16){
    int d = 0;
    for (int i = 0; i < n; ++i) d += (sAc[i*16 + tid] != 0.f);
    sDeg[tid] = fmaxf((float)d, 1.f);
  }
  __syncthreads();

  int jt = tid >> 4, c0 = (tid & 15) * 8;
  float acc[8] = {0,0,0,0,0,0,0,0};
  for (int k = 0; k < n; ++k){
    float a = sAc[k*16 + jt];
    if (a != 0.f) fma8(a, &sH[k*128 + c0], acc);
  }
  {
    float invd = 1.f / sDeg[jt];
    int j = j0 + jt;
#pragma unroll
    for (int u = 0; u < 8; ++u){
      sAgg[(c0+u)*17 + jt] = acc[u] * invd;
      sHt [(c0+u)*17 + jt] = (j < n) ? sH[j*128 + c0 + u] : 0.f;
    }
  }
  __syncthreads();
  {
    const float4* w4 = (const float4*)wtrel;
    float4* s4 = (float4*)sW;
    for (int i4 = tid; i4 < Cin*32; i4 += 256) s4[i4] = w4[i4];
  }
  __syncthreads();
  float acc2[8] = {0,0,0,0,0,0,0,0};
  for (int k = 0; k < Cin; ++k)
    fma8(sAgg[k*17 + jt], &sW[k*128 + c0], acc2);
  __syncthreads();
  {
    const float4* w4 = (const float4*)wtroot;
    float4* s4 = (float4*)sW;
    for (int i4 = tid; i4 < Cin*32; i4 += 256) s4[i4] = w4[i4];
  }
  __syncthreads();
  for (int k = 0; k < Cin; ++k){
    float a = sHt[k*17 + jt];
    if (a != 0.f) fma8(a, &sW[k*128 + c0], acc2);
  }

  int j = j0 + jt;
  if (j < n){
#pragma unroll
    for (int u = 0; u < 8; ++u){
      float v = fmaxf(acc2[u] + __ldg(brel + c0 + u), 0.f);
      houtg[j*128 + c0 + u] = v;
      sAgg[(c0+u)*17 + jt] = v;
    }
  } else {
#pragma unroll
    for (int u = 0; u < 8; ++u) sAgg[(c0+u)*17 + jt] = 0.f;
  }
  __syncthreads();
  if (tid < 128){
    float s = 0.f;
#pragma unroll
    for (int q = 0; q < 16; ++q) s += sAgg[tid*17 + q];
    atomicAdd(&g_xs[g*640 + slot*128 + tid], s * invn);
  }
}

__device__ void dv_poolq(float* sm, int g, int r, int tid,
                         const float* __restrict__ hg, const float* __restrict__ wt,
                         const float* __restrict__ linb, const float* __restrict__ attw, int n)
{
  float* sH  = sm;
  float* sW  = sm + 16384;
  float* sAc = sm + 32768;
  float* sQt = sm + 34816;
  float* sQr = sm + 36992;   // 16*136
  int j0 = r*16;
  if (j0 >= n) return;

  {
    const float4* h4 = (const float4*)hg;
    float4* s4 = (float4*)sH;
    for (int i4 = tid; i4 < n*32; i4 += 256) s4[i4] = h4[i4];
  }
  for (int idx = tid; idx < n*16; idx += 256){
    int i = idx >> 4, jt2 = idx & 15;
    int j = j0 + jt2;
    sAc[idx] = (j < n) ? g_A[g*GS + i*128 + j] : 0.f;
  }
  {
    const float4* w4 = (const float4*)wt;
    float4* s4 = (float4*)sW;
    for (int i4 = tid; i4 < 4096; i4 += 256) s4[i4] = w4[i4];
  }
  __syncthreads();

  int jt = tid >> 4, c0 = (tid & 15) * 8;
  float mx[8];
#pragma unroll
  for (int u = 0; u < 8; ++u) mx[u] = -1e30f;
  for (int i = 0; i < n; ++i){
    if (sAc[i*16 + jt] != 0.f){
      float4 b0 = *(const float4*)&sH[i*128 + c0];
      float4 b1 = *(const float4*)&sH[i*128 + c0 + 4];
      mx[0]=fmaxf(mx[0],b0.x); mx[1]=fmaxf(mx[1],b0.y);
      mx[2]=fmaxf(mx[2],b0.z); mx[3]=fmaxf(mx[3],b0.w);
      mx[4]=fmaxf(mx[4],b1.x); mx[5]=fmaxf(mx[5],b1.y);
      mx[6]=fmaxf(mx[6],b1.z); mx[7]=fmaxf(mx[7],b1.w);
    }
  }
#pragma unroll
  for (int u = 0; u < 8; ++u) sQt[(c0+u)*17 + jt] = mx[u];
  __syncthreads();

  float acc[8] = {0,0,0,0,0,0,0,0};
  for (int k = 0; k < 128; ++k)
    fma8(sQt[k*17 + jt], &sW[k*128 + c0], acc);
#pragma unroll
  for (int u = 0; u < 8; ++u) sQr[jt*136 + c0 + u] = acc[u] + __ldg(linb + c0 + u);
  __syncthreads();

  if (tid < 16){
    int j = j0 + tid;
    if (j < n){
      float sq = 0.f, sx = 0.f;
      for (int c = 0; c < 128; ++c){
        sq = fmaf(sQr[tid*136 + c], __ldg(attw + c), sq);
        sx = fmaf(sH[j*128 + c],    __ldg(attw + 128 + c), sx);
      }
      g_aq[g*128 + j] = sq;
      g_ax[g*128 + j] = sx;
    }
  }
}

__device__ void dv_smaxx(float* sm, int g, int r, int tid,
                         const float* __restrict__ hg, const float* __restrict__ attb, int p, int n)
{
  float* sH  = sm;
  float* sAc = sm + 32768;
  float* sS  = sm + 34816;
  float* sax = sm + 39184;
  float* sInv= sm + 39312;
  int j0 = r*16;
  if (j0 >= n) return;

  {
    const float4* h4 = (const float4*)hg;
    float4* s4 = (float4*)sH;
    for (int i4 = tid; i4 < n*32; i4 += 256) s4[i4] = h4[i4];
  }
  for (int idx = tid; idx < n*16; idx += 256){
    int i = idx >> 4, jt2 = idx & 15;
    int j = j0 + jt2;
    sAc[idx] = (j < n) ? g_A[g*GS + i*128 + j] : 0.f;
  }
  if (tid < n) sax[tid] = g_ax[g*128 + tid];
  __syncthreads();

  if (tid < 16){
    int j = j0 + tid;
    if (j < n){
      float ajq = g_aq[g*128 + j] + __ldg(attb + p);
      float mxv = -1e30f;
      for (int i = 0; i < n; ++i){
        if (sAc[i*16 + tid] != 0.f){
          float l = sax[i] + ajq;
          l = (l >= 0.f) ? l : 0.2f*l;
          mxv = fmaxf(mxv, l);
        }
      }
      float Z = 0.f;
      for (int i = 0; i < n; ++i){
        float s = 0.f;
        if (sAc[i*16 + tid] != 0.f){
          float l = sax[i] + ajq;
          l = (l >= 0.f) ? l : 0.2f*l;
          s = expf(l - mxv);
          Z += s;
        }
        sS[i*17 + tid] = s;
      }
      sInv[tid] = 1.f / Z;
    } else sInv[tid] = 0.f;
  }
  __syncthreads();

  for (int idx = tid; idx < n*16; idx += 256){
    int i = idx >> 4, jj = idx & 15;
    int j = j0 + jj;
    if (j < n) g_S[g*GS + i*128 + j] = sS[i*17 + jj] * sInv[jj];
  }
  int jt = tid >> 4, c0 = (tid & 15) * 8;
  float acc[8] = {0,0,0,0,0,0,0,0};
  for (int k = 0; k < n; ++k){
    float a = sS[k*17 + jt];
    if (a != 0.f) fma8(a, &sH[k*128 + c0], acc);
  }
  int j = j0 + jt;
  if (j < n){
    float inv = sInv[jt];
#pragma unroll
    for (int u = 0; u < 8; ++u) g_x2[g*GS + j*128 + c0 + u] = acc[u] * inv;
  }
}

__device__ void dv_fitk(float* sm, int g, int tid,
                        const float* __restrict__ le1w, const float* __restrict__ le1b,
                        const float* __restrict__ le2w, const float* __restrict__ le3w,
                        const float* __restrict__ le3b, int p, int n, int k)
{
  float* sa  = sm + 39328;
  float* sb  = sm + 39456;
  float* sfit= sm + 39584;
  int j = tid;
  if (j < 128){
    float av = 0.f, bv = 0.f, c3 = 0.f;
    if (j < n){
      const float* X = g_x2 + g*GS + j*128;
      for (int c = 0; c < 128; ++c){
        float xv = X[c];
        av = fmaf(xv, __ldg(le1w + c), av);
        bv = fmaf(xv, __ldg(le2w + c), bv);
        c3 = fmaf(xv, __ldg(le3w + c), c3);
      }
      av += __ldg(le1b + p);
    }
    sa[j] = av; sb[j] = bv;
    sfit[j] = -3.4e38f;
    (void)c3;
    if (j < n){
      // recompute c3 kept in register; store temporarily in sfit later
    }
  }
  __syncthreads();
  if (j < n){
    // recompute c3 (cheap) to avoid extra smem
    const float* X = g_x2 + g*GS + j*128;
    float c3 = 0.f;
    for (int c = 0; c < 128; ++c) c3 = fmaf(X[c], __ldg(le3w + c), c3);
    const float* Ab = g_A + g*GS;
    float s = 0.f, deg = 0.f;
    for (int i = 0; i < n; ++i){
      if (Ab[i*128 + j] != 0.f){ s += sa[i]; deg += 1.f; }
    }
    float f = s - deg*sb[j] + c3 + __ldg(le3b + p);
    float ff = 1.f / (1.f + expf(-f));
    sfit[j] = ff;
    g_fit[g*128 + j] = ff;
  }
  __syncthreads();
  if (j < 32){
    int lane = j;
    float v[4]; bool used[4];
#pragma unroll
    for (int s2 = 0; s2 < 4; ++s2){ v[s2] = sfit[lane + 32*s2]; used[s2] = false; }
    for (int r = 0; r < k; ++r){
      float bvv = -3.4e38f; int bi = 1 << 30;
#pragma unroll
      for (int s2 = 0; s2 < 4; ++s2){
        if (!used[s2]){
          int jj = lane + 32*s2;
          float xv = v[s2];
          if (xv > bvv || (xv == bvv && jj < bi)){ bvv = xv; bi = jj; }
        }
      }
#pragma unroll
      for (int off = 16; off; off >>= 1){
        float ov = __shfl_xor_sync(0xffffffffu, bvv, off);
        int   oi = __shfl_xor_sync(0xffffffffu, bi, off);
        if (ov > bvv || (ov == bvv && oi < bi)){ bvv = ov; bi = oi; }
      }
      if ((bi & 31) == lane) used[bi >> 5] = true;
      if (lane == 0) g_perm[g*128 + r] = bi;
    }
  }
}

__device__ void dv_aS(float* sm, int g, int r, int tid, float* __restrict__ houtg, int n, int k)
{
  float* sSel = sm;
  float* sAt  = sm + 34816;
  int*   sperm= (int*)(sm + 39712);
  int i0 = r*16;
  if (i0 >= n) return;
  if (tid < k) sperm[tid] = g_perm[g*128 + tid];
  __syncthreads();
  for (int idx = tid; idx < n*128; idx += 256){
    int m = idx >> 7, rr = idx & 127;
    sSel[idx] = (rr < k) ? g_S[g*GS + m*128 + sperm[rr]] : 0.f;
  }
  for (int idx = tid; idx < 16*128; idx += 256){
    int it = idx >> 7, m = idx & 127;
    sAt[m*17 + it] = g_A[g*GS + (i0+it)*128 + m];
  }
  __syncthreads();
  int it = tid >> 4, r0 = (tid & 15) * 8;
  float acc[8] = {0,0,0,0,0,0,0,0};
  for (int m = 0; m < n; ++m){
    float a = sAt[m*17 + it];
    if (a != 0.f) fma8(a, &sSel[m*128 + r0], acc);
  }
  int i = i0 + it;
  if (i < n){
#pragma unroll
    for (int u = 0; u < 8; ++u) g_T[g*GS + i*128 + r0 + u] = acc[u];
  }
  for (int idx = tid; idx < 16*128; idx += 256){
    int rt = idx >> 7, c = idx & 127;
    int rr = i0 + rt;
    if (rr < k){
      int pj = sperm[rr];
      houtg[rr*128 + c] = g_x2[g*GS + pj*128 + c] * g_fit[g*128 + pj];
    }
  }
}

__device__ void dv_sTs(float* sm, int g, int r, int tid, int n, int k)
{
  float* sT  = sm;
  float* sSa = sm + 34816;
  int*   sperm= (int*)(sm + 39712);
  int r0 = r*16;
  if (r0 >= k) return;
  if (tid < k) sperm[tid] = g_perm[g*128 + tid];
  __syncthreads();
  {
    const float4* t4 = (const float4*)(g_T + g*GS);
    float4* s4 = (float4*)sT;
    for (int i4 = tid; i4 < n*32; i4 += 256) s4[i4] = t4[i4];
  }
  for (int idx = tid; idx < n*16; idx += 256){
    int i = idx >> 4, rt2 = idx & 15;
    int rr = r0 + rt2;
    sSa[i*17 + rt2] = (rr < k) ? g_S[g*GS + i*128 + sperm[rr]] : 0.f;
  }
  __syncthreads();
  int rt = tid >> 4, c0 = (tid & 15) * 8;
  float acc[8] = {0,0,0,0,0,0,0,0};
  for (int i = 0; i < n; ++i){
    float a = sSa[i*17 + rt];
    if (a != 0.f) fma8(a, &sT[i*128 + c0], acc);
  }
  int rr = r0 + rt;
  if (rr < k){
#pragma unroll
    for (int u = 0; u < 8; ++u){
      int r2 = c0 + u;
      float v = (r2 == rr) ? 1.f : acc[u];
      g_A[g*GS + rr*128 + r2] = (r2 < k) ? v : 0.f;
    }
  }
}

__device__ void dv_head(float* sm, int g, int tid,
                        const float* __restrict__ b1, const float* __restrict__ w2,
                        const float* __restrict__ b2, float* __restrict__ out)
{
  float* sJ = sm;
  float* z1 = sm + 640;
  float* z2 = sm + 768;
  for (int c = tid; c < 640; c += 256) sJ[c] = g_xs[g*640 + c];
  __syncthreads();
  if (tid < 128){
    float s = __ldg(b1 + tid);
    for (int c = 0; c < 640; ++c) s = fmaf(sJ[c], g_w1t[c*128 + tid], s);
    z1[tid] = fmaxf(s, 0.f);
  }
  __syncthreads();
  if (tid < 2){
    float s2 = __ldg(b2 + tid);
    for (int c = 0; c < 128; ++c) s2 = fmaf(z1[c], __ldg(w2 + tid*128 + c), s2);
    z2[tid] = s2;
  }
  __syncthreads();
  if (tid == 0){
    float m = fmaxf(z2[0], z2[1]);
    float lse = m + logf(expf(z2[0] - m) + expf(z2[1] - m));
    out[g*2 + 0] = z2[0] - lse;
    out[g*2 + 1] = z2[1] - lse;
  }
}

// ---------------- the fused cluster kernel ----------------
__global__ void __cluster_dims__(CLU,1,1) __launch_bounds__(256,1)
k_fused(const float* __restrict__ x, const int* __restrict__ ei, int E,
        const float* __restrict__ c0_brel, const float* __restrict__ cb_rel,
        const float* __restrict__ p_lin_b, const float* __restrict__ p_att_w,
        const float* __restrict__ p_att_b,
        const float* __restrict__ p_le1_w, const float* __restrict__ p_le1_b,
        const float* __restrict__ p_le2_w, const float* __restrict__ p_le3_w,
        const float* __restrict__ p_le3_b,
        const float* __restrict__ lin1_b, const float* __restrict__ lin2_w,
        const float* __restrict__ lin2_b, float* __restrict__ out)
{
  extern __shared__ float sm[];
  int g = blockIdx.x >> 3, r = blockIdx.x & 7, tid = threadIdx.x;
  float* hA = g_h  + g*GS;
  float* hB = g_hb + g*GS;

  // S0: zero A block + xs, then scatter edges
  for (int i = r*256 + tid; i < GS; i += CLU*256) g_A[g*GS + i] = 0.f;
  for (int i = r*256 + tid; i < 640; i += CLU*256) g_xs[g*640 + i] = 0.f;
  CLUSTER_SYNC();
  int Eg = E / NG;
  for (int e = g*Eg + r*256 + tid; e < (g+1)*Eg; e += CLU*256){
    int u = ei[e], v = ei[E + e];
    atomicAdd(&g_A[g*GS + (u & 127)*128 + (v & 127)], 1.0f);
  }
  CLUSTER_SYNC();

  // conv0 (64->128): x -> hA
  dv_conv(sm, g, r, tid, x + g*128*64, 64, hA, g_wt + 0*GS, g_wt + 1*GS, c0_brel, 0, 128, 64, 1.f/128.f);
  CLUSTER_SYNC();
  // conv i=0: hA -> hB
  dv_conv(sm, g, r, tid, hA, 128, hB, g_wt + 2*GS, g_wt + 6*GS, cb_rel + 0, 1, 128, 128, 1.f/128.f);
  CLUSTER_SYNC();

  // ---- pool 1 (128 -> 103), h=hB, x_out -> hA ----
  if (r == 0 && tid < 128) g_A[g*GS + tid*128 + tid] = 1.f;
  CLUSTER_SYNC();
  dv_poolq(sm, g, r, tid, hB, g_wt + 10*GS, p_lin_b + 0, p_att_w + 0, 128);
  CLUSTER_SYNC();
  dv_smaxx(sm, g, r, tid, hB, p_att_b, 0, 128);
  CLUSTER_SYNC();
  if (r == 0) dv_fitk(sm, g, tid, p_le1_w + 0, p_le1_b, p_le2_w + 0, p_le3_w + 0, p_le3_b, 0, 128, 103);
  CLUSTER_SYNC();
  dv_aS(sm, g, r, tid, hA, 128, 103);
  CLUSTER_SYNC();
  dv_sTs(sm, g, r, tid, 128, 103);
  CLUSTER_SYNC();

  // conv i=1: hA -> hB (n=103)
  dv_conv(sm, g, r, tid, hA, 128, hB, g_wt + 3*GS, g_wt + 7*GS, cb_rel + 128, 2, 103, 128, 1.f/103.f);
  CLUSTER_SYNC();
  // conv i=2: hB -> hA
  dv_conv(sm, g, r, tid, hB, 128, hA, g_wt + 4*GS, g_wt + 8*GS, cb_rel + 256, 3, 103, 128, 1.f/103.f);
  CLUSTER_SYNC();

  // ---- pool 2 (103 -> 83), h=hA, x_out -> hB ----
  dv_poolq(sm, g, r, tid, hA, g_wt + 11*GS, p_lin_b + 128, p_att_w + 256, 103);
  CLUSTER_SYNC();
  dv_smaxx(sm, g, r, tid, hA, p_att_b, 1, 103);
  CLUSTER_SYNC();
  if (r == 0) dv_fitk(sm, g, tid, p_le1_w + 128, p_le1_b, p_le2_w + 128, p_le3_w + 128, p_le3_b, 1, 103, 83);
  CLUSTER_SYNC();
  dv_aS(sm, g, r, tid, hB, 103, 83);
  CLUSTER_SYNC();
  dv_sTs(sm, g, r, tid, 103, 83);
  CLUSTER_SYNC();

  // conv i=3: hB -> hA (n=83)
  dv_conv(sm, g, r, tid, hB, 128, hA, g_wt + 5*GS, g_wt + 9*GS, cb_rel + 384, 4, 83, 128, 1.f/83.f);
  CLUSTER_SYNC();

  if (r == 0) dv_head(sm, g, tid, lin1_b, lin2_w, lin2_b, out);
}

// ---------------- host orchestration ----------------
extern "C" void kernel_launch(void* const* d_in, const int* in_sizes, int n_in,
                              void* d_out, int out_size)
{
  const float* x        = (const float*)d_in[0];
  const int*   ei       = (const int*)  d_in[1];
  const float* c0_wrel  = (const float*)d_in[2];
  const float* c0_brel  = (const float*)d_in[3];
  const float* c0_wroot = (const float*)d_in[4];
  const float* cw_rel   = (const float*)d_in[5];
  const float* cb_rel   = (const float*)d_in[6];
  const float* cw_root  = (const float*)d_in[7];
  const float* p_lin_w  = (const float*)d_in[8];
  const float* p_lin_b  = (const float*)d_in[9];
  const float* p_att_w  = (const float*)d_in[10];
  const float* p_att_b  = (const float*)d_in[11];
  const float* p_le1_w  = (const float*)d_in[12];
  const float* p_le1_b  = (const float*)d_in[13];
  const float* p_le2_w  = (const float*)d_in[14];
  const float* p_le3_w  = (const float*)d_in[15];
  const float* p_le3_b  = (const float*)d_in[16];
  const float* lin1_w   = (const float*)d_in[17];
  const float* lin1_b   = (const float*)d_in[18];
  const float* lin2_w   = (const float*)d_in[19];
  const float* lin2_b   = (const float*)d_in[20];

  static int inited = 0;
  const size_t SMB = (size_t)SMF * 4;
  if (!inited){
    cudaFuncSetAttribute(k_fused, cudaFuncAttributeMaxDynamicSharedMemorySize, (int)SMB);
    inited = 1;
  }

  int E = in_sizes[1] / 2;

  // prep: 12*16384 + 640*128 = 278528 elements -> 1088 blocks of 256
  k_prep<<<1088, 256>>>(c0_wrel, c0_wroot, cw_rel, cw_root, p_lin_w, lin1_w);
  k_fused<<<NG*CLU, 256, SMB>>>(x, ei, E, c0_brel, cb_rel,
                                p_lin_b, p_att_w, p_att_b,
                                p_le1_w, p_le1_b, p_le2_w, p_le3_w, p_le3_b,
                                lin1_b, lin2_w, lin2_b, (float*)d_out);
}

// round 4
// speedup vs baseline: 1.0008x; 1.0008x over previous
#include <cuda_runtime.h>
#include <math.h>

#define NG 16
#define GS 16384   // 128*128 block stride
#define CLU 8

// ---------------- device scratch ----------------
__device__ float g_A [NG*GS];
__device__ float g_h [NG*GS];
__device__ float g_hb[NG*GS];
__device__ float g_x2[NG*GS];
__device__ float g_S [NG*GS];
__device__ float g_T [NG*GS];
__device__ float g_wt[12*GS];
__device__ float g_w1t[640*128];
__device__ float g_xs[NG*5*128];
__device__ float g_fit[NG*128];
__device__ float g_ax[NG*128];
__device__ float g_aq[NG*128];
__device__ int   g_perm[NG*128];

#define CLUSTER_SYNC() do{ \
  asm volatile("barrier.cluster.arrive.aligned;" ::: "memory"); \
  asm volatile("barrier.cluster.wait.aligned;"   ::: "memory"); }while(0)

__device__ __forceinline__ void fma8(float a, const float* b, float acc[8]){
  float4 b0 = *(const float4*)b;
  float4 b1 = *(const float4*)(b+4);
  acc[0]=fmaf(a,b0.x,acc[0]); acc[1]=fmaf(a,b0.y,acc[1]);
  acc[2]=fmaf(a,b0.z,acc[2]); acc[3]=fmaf(a,b0.w,acc[3]);
  acc[4]=fmaf(a,b1.x,acc[4]); acc[5]=fmaf(a,b1.y,acc[5]);
  acc[6]=fmaf(a,b1.z,acc[6]); acc[7]=fmaf(a,b1.w,acc[7]);
}

// smem carve (floats):
// 0     sH     16384
// 16384 sW     16384
// 32768 sAc     2048
// 34816 sAgg    2176   (also sS / sAt / sSa / sQt)
// 36992 sHt     2176   (also sQr)
// 39168 sDeg      16
// 39184 sax      128
// 39312 sInv      16
// 39328 sa       128
// 39456 sb       128
// 39584 sfit     128
// 39712 sperm    128 (int)
#define SMF 39840

// ---------------- prep: weight transposes ----------------
__global__ void k_prep(const float* __restrict__ c0r, const float* __restrict__ c0t,
                       const float* __restrict__ cwr, const float* __restrict__ cwt,
                       const float* __restrict__ plw, const float* __restrict__ w1){
  int idx = blockIdx.x*256 + threadIdx.x;
  if (idx < 12*GS){
    int slot = idx >> 14, e = idx & 16383;
    int c = e >> 7, o = e & 127;
    const float* src; int Cin;
    if (slot == 0){ src = c0r; Cin = 64; }
    else if (slot == 1){ src = c0t; Cin = 64; }
    else if (slot < 6){ src = cwr + (slot-2)*GS; Cin = 128; }
    else if (slot < 10){ src = cwt + (slot-6)*GS; Cin = 128; }
    else { src = plw + (slot-10)*GS; Cin = 128; }
    g_wt[idx] = (c < Cin) ? src[o*Cin + c] : 0.f;
  } else if (idx < 12*GS + 640*128){
    int j = idx - 12*GS;
    int c = j >> 7, o = j & 127;
    g_w1t[j] = w1[o*640 + c];
  }
}

// ---------------- stage device functions ----------------
__device__ void dv_conv(float* sm, int g, int r, int tid,
                        const float* __restrict__ X, int ld_in,
                        float* __restrict__ houtg,
                        const float* __restrict__ wtrel, const float* __restrict__ wtroot,
                        const float* __restrict__ brel, int slot, int n, int Cin, float invn)
{
  float* sH  = sm;
  float* sW  = sm + 16384;
  float* sAc = sm + 32768;
  float* sAgg= sm + 34816;
  float* sHt = sm + 36992;
  float* sDeg= sm + 39168;
  int j0 = r*16;
  if (j0 >= n) return;

  if (Cin == 128){
    const float4* s4 = (const float4*)X;
    float4* d4 = (float4*)sH;
    for (int i4 = tid; i4 < n*32; i4 += 256) d4[i4] = s4[i4];
  } else {
    for (int idx = tid; idx < n*128; idx += 256){
      int i = idx >> 7, c = idx & 127;
      sH[idx] = (c < Cin) ? X[i*ld_in + c] : 0.f;
    }
  }
  for (int idx = tid; idx < n*16; idx += 256){
    int i = idx >> 4, jt = idx & 15;
    int j = j0 + jt;
    sAc[idx] = (j < n) ? g_A[g*GS + i*128 + j] : 0.f;
  }
  __syncthreads();
  if (tid < 16){
    int d = 0;
    for (int i = 0; i < n; ++i) d += (sAc[i*16 + tid] != 0.f);
    sDeg[tid] = fmaxf((float)d, 1.f);
  }
  __syncthreads();

  int jt = tid >> 4, c0 = (tid & 15) * 8;
  float acc[8] = {0,0,0,0,0,0,0,0};
  for (int k = 0; k < n; ++k){
    float a = sAc[k*16 + jt];
    if (a != 0.f) fma8(a, &sH[k*128 + c0], acc);
  }
  {
    float invd = 1.f / sDeg[jt];
    int j = j0 + jt;
#pragma unroll
    for (int u = 0; u < 8; ++u){
      sAgg[(c0+u)*17 + jt] = acc[u] * invd;
      sHt [(c0+u)*17 + jt] = (j < n) ? sH[j*128 + c0 + u] : 0.f;
    }
  }
  __syncthreads();
  {
    const float4* w4 = (const float4*)wtrel;
    float4* s4 = (float4*)sW;
    for (int i4 = tid; i4 < Cin*32; i4 += 256) s4[i4] = w4[i4];
  }
  __syncthreads();
  float acc2[8] = {0,0,0,0,0,0,0,0};
  for (int k = 0; k < Cin; ++k)
    fma8(sAgg[k*17 + jt], &sW[k*128 + c0], acc2);
  __syncthreads();
  {
    const float4* w4 = (const float4*)wtroot;
    float4* s4 = (float4*)sW;
    for (int i4 = tid; i4 < Cin*32; i4 += 256) s4[i4] = w4[i4];
  }
  __syncthreads();
  for (int k = 0; k < Cin; ++k){
    float a = sHt[k*17 + jt];
    if (a != 0.f) fma8(a, &sW[k*128 + c0], acc2);
  }

  int j = j0 + jt;
  if (j < n){
#pragma unroll
    for (int u = 0; u < 8; ++u){
      float v = fmaxf(acc2[u] + __ldg(brel + c0 + u), 0.f);
      houtg[j*128 + c0 + u] = v;
      sAgg[(c0+u)*17 + jt] = v;
    }
  } else {
#pragma unroll
    for (int u = 0; u < 8; ++u) sAgg[(c0+u)*17 + jt] = 0.f;
  }
  __syncthreads();
  if (tid < 128){
    float s = 0.f;
#pragma unroll
    for (int q = 0; q < 16; ++q) s += sAgg[tid*17 + q];
    atomicAdd(&g_xs[g*640 + slot*128 + tid], s * invn);
  }
}

__device__ void dv_poolq(float* sm, int g, int r, int tid,
                         const float* __restrict__ hg, const float* __restrict__ wt,
                         const float* __restrict__ linb, const float* __restrict__ attw, int n)
{
  float* sH  = sm;
  float* sW  = sm + 16384;
  float* sAc = sm + 32768;
  float* sQt = sm + 34816;
  float* sQr = sm + 36992;   // 16*136
  int j0 = r*16;
  if (j0 >= n) return;

  {
    const float4* h4 = (const float4*)hg;
    float4* s4 = (float4*)sH;
    for (int i4 = tid; i4 < n*32; i4 += 256) s4[i4] = h4[i4];
  }
  for (int idx = tid; idx < n*16; idx += 256){
    int i = idx >> 4, jt2 = idx & 15;
    int j = j0 + jt2;
    sAc[idx] = (j < n) ? g_A[g*GS + i*128 + j] : 0.f;
  }
  {
    const float4* w4 = (const float4*)wt;
    float4* s4 = (float4*)sW;
    for (int i4 = tid; i4 < 4096; i4 += 256) s4[i4] = w4[i4];
  }
  __syncthreads();

  int jt = tid >> 4, c0 = (tid & 15) * 8;
  float mx[8];
#pragma unroll
  for (int u = 0; u < 8; ++u) mx[u] = -1e30f;
  for (int i = 0; i < n; ++i){
    if (sAc[i*16 + jt] != 0.f){
      float4 b0 = *(const float4*)&sH[i*128 + c0];
      float4 b1 = *(const float4*)&sH[i*128 + c0 + 4];
      mx[0]=fmaxf(mx[0],b0.x); mx[1]=fmaxf(mx[1],b0.y);
      mx[2]=fmaxf(mx[2],b0.z); mx[3]=fmaxf(mx[3],b0.w);
      mx[4]=fmaxf(mx[4],b1.x); mx[5]=fmaxf(mx[5],b1.y);
      mx[6]=fmaxf(mx[6],b1.z); mx[7]=fmaxf(mx[7],b1.w);
    }
  }
#pragma unroll
  for (int u = 0; u < 8; ++u) sQt[(c0+u)*17 + jt] = mx[u];
  __syncthreads();

  float acc[8] = {0,0,0,0,0,0,0,0};
  for (int k = 0; k < 128; ++k)
    fma8(sQt[k*17 + jt], &sW[k*128 + c0], acc);
#pragma unroll
  for (int u = 0; u < 8; ++u) sQr[jt*136 + c0 + u] = acc[u] + __ldg(linb + c0 + u);
  __syncthreads();

  if (tid < 16){
    int j = j0 + tid;
    if (j < n){
      float sq = 0.f, sx = 0.f;
      for (int c = 0; c < 128; ++c){
        sq = fmaf(sQr[tid*136 + c], __ldg(attw + c), sq);
        sx = fmaf(sH[j*128 + c],    __ldg(attw + 128 + c), sx);
      }
      g_aq[g*128 + j] = sq;
      g_ax[g*128 + j] = sx;
    }
  }
}

__device__ void dv_smaxx(float* sm, int g, int r, int tid,
                         const float* __restrict__ hg, const float* __restrict__ attb, int p, int n)
{
  float* sH  = sm;
  float* sAc = sm + 32768;
  float* sS  = sm + 34816;
  float* sax = sm + 39184;
  float* sInv= sm + 39312;
  int j0 = r*16;
  if (j0 >= n) return;

  {
    const float4* h4 = (const float4*)hg;
    float4* s4 = (float4*)sH;
    for (int i4 = tid; i4 < n*32; i4 += 256) s4[i4] = h4[i4];
  }
  for (int idx = tid; idx < n*16; idx += 256){
    int i = idx >> 4, jt2 = idx & 15;
    int j = j0 + jt2;
    sAc[idx] = (j < n) ? g_A[g*GS + i*128 + j] : 0.f;
  }
  if (tid < n) sax[tid] = g_ax[g*128 + tid];
  __syncthreads();

  if (tid < 16){
    int j = j0 + tid;
    if (j < n){
      float ajq = g_aq[g*128 + j] + __ldg(attb + p);
      float mxv = -1e30f;
      for (int i = 0; i < n; ++i){
        if (sAc[i*16 + tid] != 0.f){
          float l = sax[i] + ajq;
          l = (l >= 0.f) ? l : 0.2f*l;
          mxv = fmaxf(mxv, l);
        }
      }
      float Z = 0.f;
      for (int i = 0; i < n; ++i){
        float s = 0.f;
        if (sAc[i*16 + tid] != 0.f){
          float l = sax[i] + ajq;
          l = (l >= 0.f) ? l : 0.2f*l;
          s = expf(l - mxv);
          Z += s;
        }
        sS[i*17 + tid] = s;
      }
      sInv[tid] = 1.f / Z;
    } else sInv[tid] = 0.f;
  }
  __syncthreads();

  for (int idx = tid; idx < n*16; idx += 256){
    int i = idx >> 4, jj = idx & 15;
    int j = j0 + jj;
    if (j < n) g_S[g*GS + i*128 + j] = sS[i*17 + jj] * sInv[jj];
  }
  int jt = tid >> 4, c0 = (tid & 15) * 8;
  float acc[8] = {0,0,0,0,0,0,0,0};
  for (int k = 0; k < n; ++k){
    float a = sS[k*17 + jt];
    if (a != 0.f) fma8(a, &sH[k*128 + c0], acc);
  }
  int j = j0 + jt;
  if (j < n){
    float inv = sInv[jt];
#pragma unroll
    for (int u = 0; u < 8; ++u) g_x2[g*GS + j*128 + c0 + u] = acc[u] * inv;
  }
}

__device__ void dv_fitk(float* sm, int g, int tid,
                        const float* __restrict__ le1w, const float* __restrict__ le1b,
                        const float* __restrict__ le2w, const float* __restrict__ le3w,
                        const float* __restrict__ le3b, int p, int n, int k)
{
  float* sa  = sm + 39328;
  float* sb  = sm + 39456;
  float* sfit= sm + 39584;
  int j = tid;
  if (j < 128){
    float av = 0.f, bv = 0.f, c3 = 0.f;
    if (j < n){
      const float* X = g_x2 + g*GS + j*128;
      for (int c = 0; c < 128; ++c){
        float xv = X[c];
        av = fmaf(xv, __ldg(le1w + c), av);
        bv = fmaf(xv, __ldg(le2w + c), bv);
        c3 = fmaf(xv, __ldg(le3w + c), c3);
      }
      av += __ldg(le1b + p);
    }
    sa[j] = av; sb[j] = bv;
    sfit[j] = -3.4e38f;
    (void)c3;
    if (j < n){
      // recompute c3 kept in register; store temporarily in sfit later
    }
  }
  __syncthreads();
  if (j < n){
    // recompute c3 (cheap) to avoid extra smem
    const float* X = g_x2 + g*GS + j*128;
    float c3 = 0.f;
    for (int c = 0; c < 128; ++c) c3 = fmaf(X[c], __ldg(le3w + c), c3);
    const float* Ab = g_A + g*GS;
    float s = 0.f, deg = 0.f;
    for (int i = 0; i < n; ++i){
      if (Ab[i*128 + j] != 0.f){ s += sa[i]; deg += 1.f; }
    }
    float f = s - deg*sb[j] + c3 + __ldg(le3b + p);
    float ff = 1.f / (1.f + expf(-f));
    sfit[j] = ff;
    g_fit[g*128 + j] = ff;
  }
  __syncthreads();
  if (j < 32){
    int lane = j;
    float v[4]; bool used[4];
#pragma unroll
    for (int s2 = 0; s2 < 4; ++s2){ v[s2] = sfit[lane + 32*s2]; used[s2] = false; }
    for (int r = 0; r < k; ++r){
      float bvv = -3.4e38f; int bi = 1 << 30;
#pragma unroll
      for (int s2 = 0; s2 < 4; ++s2){
        if (!used[s2]){
          int jj = lane + 32*s2;
          float xv = v[s2];
          if (xv > bvv || (xv == bvv && jj < bi)){ bvv = xv; bi = jj; }
        }
      }
#pragma unroll
      for (int off = 16; off; off >>= 1){
        float ov = __shfl_xor_sync(0xffffffffu, bvv, off);
        int   oi = __shfl_xor_sync(0xffffffffu, bi, off);
        if (ov > bvv || (ov == bvv && oi < bi)){ bvv = ov; bi = oi; }
      }
      if ((bi & 31) == lane) used[bi >> 5] = true;
      if (lane == 0) g_perm[g*128 + r] = bi;
    }
  }
}

__device__ void dv_aS(float* sm, int g, int r, int tid, float* __restrict__ houtg, int n, int k)
{
  float* sSel = sm;
  float* sAt  = sm + 34816;
  int*   sperm= (int*)(sm + 39712);
  int i0 = r*16;
  if (i0 >= n) return;
  if (tid < k) sperm[tid] = g_perm[g*128 + tid];
  __syncthreads();
  for (int idx = tid; idx < n*128; idx += 256){
    int m = idx >> 7, rr = idx & 127;
    sSel[idx] = (rr < k) ? g_S[g*GS + m*128 + sperm[rr]] : 0.f;
  }
  for (int idx = tid; idx < 16*128; idx += 256){
    int it = idx >> 7, m = idx & 127;
    sAt[m*17 + it] = g_A[g*GS + (i0+it)*128 + m];
  }
  __syncthreads();
  int it = tid >> 4, r0 = (tid & 15) * 8;
  float acc[8] = {0,0,0,0,0,0,0,0};
  for (int m = 0; m < n; ++m){
    float a = sAt[m*17 + it];
    if (a != 0.f) fma8(a, &sSel[m*128 + r0], acc);
  }
  int i = i0 + it;
  if (i < n){
#pragma unroll
    for (int u = 0; u < 8; ++u) g_T[g*GS + i*128 + r0 + u] = acc[u];
  }
  for (int idx = tid; idx < 16*128; idx += 256){
    int rt = idx >> 7, c = idx & 127;
    int rr = i0 + rt;
    if (rr < k){
      int pj = sperm[rr];
      houtg[rr*128 + c] = g_x2[g*GS + pj*128 + c] * g_fit[g*128 + pj];
    }
  }
}

__device__ void dv_sTs(float* sm, int g, int r, int tid, int n, int k)
{
  float* sT  = sm;
  float* sSa = sm + 34816;
  int*   sperm= (int*)(sm + 39712);
  int r0 = r*16;
  if (r0 >= k) return;
  if (tid < k) sperm[tid] = g_perm[g*128 + tid];
  __syncthreads();
  {
    const float4* t4 = (const float4*)(g_T + g*GS);
    float4* s4 = (float4*)sT;
    for (int i4 = tid; i4 < n*32; i4 += 256) s4[i4] = t4[i4];
  }
  for (int idx = tid; idx < n*16; idx += 256){
    int i = idx >> 4, rt2 = idx & 15;
    int rr = r0 + rt2;
    sSa[i*17 + rt2] = (rr < k) ? g_S[g*GS + i*128 + sperm[rr]] : 0.f;
  }
  __syncthreads();
  int rt = tid >> 4, c0 = (tid & 15) * 8;
  float acc[8] = {0,0,0,0,0,0,0,0};
  for (int i = 0; i < n; ++i){
    float a = sSa[i*17 + rt];
    if (a != 0.f) fma8(a, &sT[i*128 + c0], acc);
  }
  int rr = r0 + rt;
  if (rr < k){
#pragma unroll
    for (int u = 0; u < 8; ++u){
      int r2 = c0 + u;
      float v = (r2 == rr) ? 1.f : acc[u];
      g_A[g*GS + rr*128 + r2] = (r2 < k) ? v : 0.f;
    }
  }
}

__device__ void dv_head(float* sm, int g, int tid,
                        const float* __restrict__ b1, const float* __restrict__ w2,
                        const float* __restrict__ b2, float* __restrict__ out)
{
  float* sJ = sm;
  float* z1 = sm + 640;
  float* z2 = sm + 768;
  for (int c = tid; c < 640; c += 256) sJ[c] = g_xs[g*640 + c];
  __syncthreads();
  if (tid < 128){
    float s = __ldg(b1 + tid);
    for (int c = 0; c < 640; ++c) s = fmaf(sJ[c], g_w1t[c*128 + tid], s);
    z1[tid] = fmaxf(s, 0.f);
  }
  __syncthreads();
  if (tid < 2){
    float s2 = __ldg(b2 + tid);
    for (int c = 0; c < 128; ++c) s2 = fmaf(z1[c], __ldg(w2 + tid*128 + c), s2);
    z2[tid] = s2;
  }
  __syncthreads();
  if (tid == 0){
    float m = fmaxf(z2[0], z2[1]);
    float lse = m + logf(expf(z2[0] - m) + expf(z2[1] - m));
    out[g*2 + 0] = z2[0] - lse;
    out[g*2 + 1] = z2[1] - lse;
  }
}

// ---------------- the fused cluster kernel ----------------
__global__ void __cluster_dims__(CLU,1,1) __launch_bounds__(256,1)
k_fused(const float* __restrict__ x, const int* __restrict__ ei, int E,
        const float* __restrict__ c0_brel, const float* __restrict__ cb_rel,
        const float* __restrict__ p_lin_b, const float* __restrict__ p_att_w,
        const float* __restrict__ p_att_b,
        const float* __restrict__ p_le1_w, const float* __restrict__ p_le1_b,
        const float* __restrict__ p_le2_w, const float* __restrict__ p_le3_w,
        const float* __restrict__ p_le3_b,
        const float* __restrict__ lin1_b, const float* __restrict__ lin2_w,
        const float* __restrict__ lin2_b, float* __restrict__ out)
{
  extern __shared__ float sm[];
  int g = blockIdx.x >> 3, r = blockIdx.x & 7, tid = threadIdx.x;
  float* hA = g_h  + g*GS;
  float* hB = g_hb + g*GS;

  // S0: zero A block + xs, then scatter edges
  for (int i = r*256 + tid; i < GS; i += CLU*256) g_A[g*GS + i] = 0.f;
  for (int i = r*256 + tid; i < 640; i += CLU*256) g_xs[g*640 + i] = 0.f;
  CLUSTER_SYNC();
  int Eg = E / NG;
  for (int e = g*Eg + r*256 + tid; e < (g+1)*Eg; e += CLU*256){
    int u = ei[e], v = ei[E + e];
    atomicAdd(&g_A[g*GS + (u & 127)*128 + (v & 127)], 1.0f);
  }
  CLUSTER_SYNC();

  // conv0 (64->128): x -> hA
  dv_conv(sm, g, r, tid, x + g*128*64, 64, hA, g_wt + 0*GS, g_wt + 1*GS, c0_brel, 0, 128, 64, 1.f/128.f);
  CLUSTER_SYNC();
  // conv i=0: hA -> hB
  dv_conv(sm, g, r, tid, hA, 128, hB, g_wt + 2*GS, g_wt + 6*GS, cb_rel + 0, 1, 128, 128, 1.f/128.f);
  CLUSTER_SYNC();

  // ---- pool 1 (128 -> 103), h=hB, x_out -> hA ----
  if (r == 0 && tid < 128) g_A[g*GS + tid*128 + tid] = 1.f;
  CLUSTER_SYNC();
  dv_poolq(sm, g, r, tid, hB, g_wt + 10*GS, p_lin_b + 0, p_att_w + 0, 128);
  CLUSTER_SYNC();
  dv_smaxx(sm, g, r, tid, hB, p_att_b, 0, 128);
  CLUSTER_SYNC();
  if (r == 0) dv_fitk(sm, g, tid, p_le1_w + 0, p_le1_b, p_le2_w + 0, p_le3_w + 0, p_le3_b, 0, 128, 103);
  CLUSTER_SYNC();
  dv_aS(sm, g, r, tid, hA, 128, 103);
  CLUSTER_SYNC();
  dv_sTs(sm, g, r, tid, 128, 103);
  CLUSTER_SYNC();

  // conv i=1: hA -> hB (n=103)
  dv_conv(sm, g, r, tid, hA, 128, hB, g_wt + 3*GS, g_wt + 7*GS, cb_rel + 128, 2, 103, 128, 1.f/103.f);
  CLUSTER_SYNC();
  // conv i=2: hB -> hA
  dv_conv(sm, g, r, tid, hB, 128, hA, g_wt + 4*GS, g_wt + 8*GS, cb_rel + 256, 3, 103, 128, 1.f/103.f);
  CLUSTER_SYNC();

  // ---- pool 2 (103 -> 83), h=hA, x_out -> hB ----
  dv_poolq(sm, g, r, tid, hA, g_wt + 11*GS, p_lin_b + 128, p_att_w + 256, 103);
  CLUSTER_SYNC();
  dv_smaxx(sm, g, r, tid, hA, p_att_b, 1, 103);
  CLUSTER_SYNC();
  if (r == 0) dv_fitk(sm, g, tid, p_le1_w + 128, p_le1_b, p_le2_w + 128, p_le3_w + 128, p_le3_b, 1, 103, 83);
  CLUSTER_SYNC();
  dv_aS(sm, g, r, tid, hB, 103, 83);
  CLUSTER_SYNC();
  dv_sTs(sm, g, r, tid, 103, 83);
  CLUSTER_SYNC();

  // conv i=3: hB -> hA (n=83)
  dv_conv(sm, g, r, tid, hB, 128, hA, g_wt + 5*GS, g_wt + 9*GS, cb_rel + 384, 4, 83, 128, 1.f/83.f);
  CLUSTER_SYNC();

  if (r == 0) dv_head(sm, g, tid, lin1_b, lin2_w, lin2_b, out);
}

// ---------------- host orchestration ----------------
extern "C" void kernel_launch(void* const* d_in, const int* in_sizes, int n_in,
                              void* d_out, int out_size)
{
  const float* x        = (const float*)d_in[0];
  const int*   ei       = (const int*)  d_in[1];
  const float* c0_wrel  = (const float*)d_in[2];
  const float* c0_brel  = (const float*)d_in[3];
  const float* c0_wroot = (const float*)d_in[4];
  const float* cw_rel   = (const float*)d_in[5];
  const float* cb_rel   = (const float*)d_in[6];
  const float* cw_root  = (const float*)d_in[7];
  const float* p_lin_w  = (const float*)d_in[8];
  const float* p_lin_b  = (const float*)d_in[9];
  const float* p_att_w  = (const float*)d_in[10];
  const float* p_att_b  = (const float*)d_in[11];
  const float* p_le1_w  = (const float*)d_in[12];
  const float* p_le1_b  = (const float*)d_in[13];
  const float* p_le2_w  = (const float*)d_in[14];
  const float* p_le3_w  = (const float*)d_in[15];
  const float* p_le3_b  = (const float*)d_in[16];
  const float* lin1_w   = (const float*)d_in[17];
  const float* lin1_b   = (const float*)d_in[18];
  const float* lin2_w   = (const float*)d_in[19];
  const float* lin2_b   = (const float*)d_in[20];

  static int inited = 0;
  const size_t SMB = (size_t)SMF * 4;
  if (!inited){
    cudaFuncSetAttribute(k_fused, cudaFuncAttributeMaxDynamicSharedMemorySize, (int)SMB);
    inited = 1;
  }

  int E = in_sizes[1] / 2;

  // prep: 12*16384 + 640*128 = 278528 elements -> 1088 blocks of 256
  k_prep<<<1088, 256>>>(c0_wrel, c0_wroot, cw_rel, cw_root, p_lin_w, lin1_w);
  k_fused<<<NG*CLU, 256, SMB>>>(x, ei, E, c0_brel, cb_rel,
                                p_lin_b, p_att_w, p_att_b,
                                p_le1_w, p_le1_b, p_le2_w, p_le3_w, p_le3_b,
                                lin1_b, lin2_w, lin2_b, (float*)d_out);
}

// round 5
// speedup vs baseline: 1.9354x; 1.9339x over previous
#include <cuda_runtime.h>
#include <math.h>

#define NG 16
#define GS 16384   // 128*128 block stride
#define NCTA 8     // CTAs per group

// ---------------- device scratch ----------------
__device__ float g_A [NG*GS];
__device__ float g_h [NG*GS];
__device__ float g_hb[NG*GS];
__device__ float g_x2[NG*GS];
__device__ float g_S [NG*GS];
__device__ float g_T [NG*GS];
__device__ float g_wt[12*GS];
__device__ float g_w1t[640*128];
__device__ float g_xs[NG*5*128];
__device__ float g_fit[NG*128];
__device__ float g_ax[NG*128];
__device__ float g_aq[NG*128];
__device__ int   g_perm[NG*128];
__device__ unsigned g_bar[NG*32];

// per-group sense barrier across NCTA CTAs (slot used once per launch; prep zeroes)
__device__ __forceinline__ void gbar(int g, int slot, int tid){
  __syncthreads();
  if (tid == 0){
    __threadfence();
    unsigned* p = &g_bar[g*32 + slot];
    atomicAdd(p, 1u);
    unsigned v;
    do {
      asm volatile("ld.acquire.gpu.u32 %0, [%1];" : "=r"(v) : "l"(p) : "memory");
    } while (v < NCTA);
  }
  __syncthreads();
}

__device__ __forceinline__ void fma8(float a, const float* b, float acc[8]){
  float4 b0 = *(const float4*)b;
  float4 b1 = *(const float4*)(b+4);
  acc[0]=fmaf(a,b0.x,acc[0]); acc[1]=fmaf(a,b0.y,acc[1]);
  acc[2]=fmaf(a,b0.z,acc[2]); acc[3]=fmaf(a,b0.w,acc[3]);
  acc[4]=fmaf(a,b1.x,acc[4]); acc[5]=fmaf(a,b1.y,acc[5]);
  acc[6]=fmaf(a,b1.z,acc[6]); acc[7]=fmaf(a,b1.w,acc[7]);
}

// smem carve (floats): see offsets below
#define SMF 39840

// ---------------- prep: weight transposes + barrier zeroing ----------------
__global__ void k_prep(const float* __restrict__ c0r, const float* __restrict__ c0t,
                       const float* __restrict__ cwr, const float* __restrict__ cwt,
                       const float* __restrict__ plw, const float* __restrict__ w1){
  int idx = blockIdx.x*256 + threadIdx.x;
  if (idx < 12*GS){
    int slot = idx >> 14, e = idx & 16383;
    int c = e >> 7, o = e & 127;
    const float* src; int Cin;
    if (slot == 0){ src = c0r; Cin = 64; }
    else if (slot == 1){ src = c0t; Cin = 64; }
    else if (slot < 6){ src = cwr + (slot-2)*GS; Cin = 128; }
    else if (slot < 10){ src = cwt + (slot-6)*GS; Cin = 128; }
    else { src = plw + (slot-10)*GS; Cin = 128; }
    g_wt[idx] = (c < Cin) ? src[o*Cin + c] : 0.f;
  } else if (idx < 12*GS + 640*128){
    int j = idx - 12*GS;
    int c = j >> 7, o = j & 127;
    g_w1t[j] = w1[o*640 + c];
  } else if (idx < 12*GS + 640*128 + NG*32){
    g_bar[idx - 12*GS - 640*128] = 0u;
  }
}

// ---------------- stage device functions (bodies proven in R3) ----------------
__device__ void dv_conv(float* sm, int g, int r, int tid,
                        const float* __restrict__ X, int ld_in,
                        float* __restrict__ houtg,
                        const float* __restrict__ wtrel, const float* __restrict__ wtroot,
                        const float* __restrict__ brel, int slot, int n, int Cin, float invn)
{
  float* sH  = sm;
  float* sW  = sm + 16384;
  float* sAc = sm + 32768;
  float* sAgg= sm + 34816;
  float* sHt = sm + 36992;
  float* sDeg= sm + 39168;
  int j0 = r*16;
  if (j0 >= n) return;

  if (Cin == 128){
    const float4* s4 = (const float4*)X;
    float4* d4 = (float4*)sH;
    for (int i4 = tid; i4 < n*32; i4 += 256) d4[i4] = __ldcg(s4 + i4);
  } else {
    for (int idx = tid; idx < n*128; idx += 256){
      int i = idx >> 7, c = idx & 127;
      sH[idx] = (c < Cin) ? __ldg(X + i*ld_in + c) : 0.f;
    }
  }
  for (int idx = tid; idx < n*16; idx += 256){
    int i = idx >> 4, jt = idx & 15;
    int j = j0 + jt;
    sAc[idx] = (j < n) ? __ldcg(g_A + g*GS + i*128 + j) : 0.f;
  }
  __syncthreads();
  if (tid < 16){
    int d = 0;
    for (int i = 0; i < n; ++i) d += (sAc[i*16 + tid] != 0.f);
    sDeg[tid] = fmaxf((float)d, 1.f);
  }
  __syncthreads();

  int jt = tid >> 4, c0 = (tid & 15) * 8;
  float acc[8] = {0,0,0,0,0,0,0,0};
  for (int k = 0; k < n; ++k){
    float a = sAc[k*16 + jt];
    if (a != 0.f) fma8(a, &sH[k*128 + c0], acc);
  }
  {
    float invd = 1.f / sDeg[jt];
    int j = j0 + jt;
#pragma unroll
    for (int u = 0; u < 8; ++u){
      sAgg[(c0+u)*17 + jt] = acc[u] * invd;
      sHt [(c0+u)*17 + jt] = (j < n) ? sH[j*128 + c0 + u] : 0.f;
    }
  }
  __syncthreads();
  {
    const float4* w4 = (const float4*)wtrel;
    float4* s4 = (float4*)sW;
    for (int i4 = tid; i4 < Cin*32; i4 += 256) s4[i4] = w4[i4];
  }
  __syncthreads();
  float acc2[8] = {0,0,0,0,0,0,0,0};
  for (int k = 0; k < Cin; ++k)
    fma8(sAgg[k*17 + jt], &sW[k*128 + c0], acc2);
  __syncthreads();
  {
    const float4* w4 = (const float4*)wtroot;
    float4* s4 = (float4*)sW;
    for (int i4 = tid; i4 < Cin*32; i4 += 256) s4[i4] = w4[i4];
  }
  __syncthreads();
  for (int k = 0; k < Cin; ++k){
    float a = sHt[k*17 + jt];
    if (a != 0.f) fma8(a, &sW[k*128 + c0], acc2);
  }

  int j = j0 + jt;
  if (j < n){
#pragma unroll
    for (int u = 0; u < 8; ++u){
      float v = fmaxf(acc2[u] + __ldg(brel + c0 + u), 0.f);
      houtg[j*128 + c0 + u] = v;
      sAgg[(c0+u)*17 + jt] = v;
    }
  } else {
#pragma unroll
    for (int u = 0; u < 8; ++u) sAgg[(c0+u)*17 + jt] = 0.f;
  }
  __syncthreads();
  if (tid < 128){
    float s = 0.f;
#pragma unroll
    for (int q = 0; q < 16; ++q) s += sAgg[tid*17 + q];
    atomicAdd(&g_xs[g*640 + slot*128 + tid], s * invn);
  }
}

__device__ void dv_poolq(float* sm, int g, int r, int tid,
                         const float* __restrict__ hg, const float* __restrict__ wt,
                         const float* __restrict__ linb, const float* __restrict__ attw, int n)
{
  float* sH  = sm;
  float* sW  = sm + 16384;
  float* sAc = sm + 32768;
  float* sQt = sm + 34816;
  float* sQr = sm + 36992;   // 16*136
  int j0 = r*16;
  if (j0 >= n) return;

  {
    const float4* h4 = (const float4*)hg;
    float4* s4 = (float4*)sH;
    for (int i4 = tid; i4 < n*32; i4 += 256) s4[i4] = __ldcg(h4 + i4);
  }
  for (int idx = tid; idx < n*16; idx += 256){
    int i = idx >> 4, jt2 = idx & 15;
    int j = j0 + jt2;
    sAc[idx] = (j < n) ? __ldcg(g_A + g*GS + i*128 + j) : 0.f;
  }
  {
    const float4* w4 = (const float4*)wt;
    float4* s4 = (float4*)sW;
    for (int i4 = tid; i4 < 4096; i4 += 256) s4[i4] = w4[i4];
  }
  __syncthreads();

  int jt = tid >> 4, c0 = (tid & 15) * 8;
  float mx[8];
#pragma unroll
  for (int u = 0; u < 8; ++u) mx[u] = -1e30f;
  for (int i = 0; i < n; ++i){
    if (sAc[i*16 + jt] != 0.f){
      float4 b0 = *(const float4*)&sH[i*128 + c0];
      float4 b1 = *(const float4*)&sH[i*128 + c0 + 4];
      mx[0]=fmaxf(mx[0],b0.x); mx[1]=fmaxf(mx[1],b0.y);
      mx[2]=fmaxf(mx[2],b0.z); mx[3]=fmaxf(mx[3],b0.w);
      mx[4]=fmaxf(mx[4],b1.x); mx[5]=fmaxf(mx[5],b1.y);
      mx[6]=fmaxf(mx[6],b1.z); mx[7]=fmaxf(mx[7],b1.w);
    }
  }
#pragma unroll
  for (int u = 0; u < 8; ++u) sQt[(c0+u)*17 + jt] = mx[u];
  __syncthreads();

  float acc[8] = {0,0,0,0,0,0,0,0};
  for (int k = 0; k < 128; ++k)
    fma8(sQt[k*17 + jt], &sW[k*128 + c0], acc);
#pragma unroll
  for (int u = 0; u < 8; ++u) sQr[jt*136 + c0 + u] = acc[u] + __ldg(linb + c0 + u);
  __syncthreads();

  if (tid < 16){
    int j = j0 + tid;
    if (j < n){
      float sq = 0.f, sx = 0.f;
      for (int c = 0; c < 128; ++c){
        sq = fmaf(sQr[tid*136 + c], __ldg(attw + c), sq);
        sx = fmaf(sH[j*128 + c],    __ldg(attw + 128 + c), sx);
      }
      g_aq[g*128 + j] = sq;
      g_ax[g*128 + j] = sx;
    }
  }
}

__device__ void dv_smaxx(float* sm, int g, int r, int tid,
                         const float* __restrict__ hg, const float* __restrict__ attb, int p, int n)
{
  float* sH  = sm;
  float* sAc = sm + 32768;
  float* sS  = sm + 34816;
  float* sax = sm + 39184;
  float* sInv= sm + 39312;
  int j0 = r*16;
  if (j0 >= n) return;

  {
    const float4* h4 = (const float4*)hg;
    float4* s4 = (float4*)sH;
    for (int i4 = tid; i4 < n*32; i4 += 256) s4[i4] = __ldcg(h4 + i4);
  }
  for (int idx = tid; idx < n*16; idx += 256){
    int i = idx >> 4, jt2 = idx & 15;
    int j = j0 + jt2;
    sAc[idx] = (j < n) ? __ldcg(g_A + g*GS + i*128 + j) : 0.f;
  }
  if (tid < n) sax[tid] = __ldcg(g_ax + g*128 + tid);
  __syncthreads();

  if (tid < 16){
    int j = j0 + tid;
    if (j < n){
      float ajq = __ldcg(g_aq + g*128 + j) + __ldg(attb + p);
      float mxv = -1e30f;
      for (int i = 0; i < n; ++i){
        if (sAc[i*16 + tid] != 0.f){
          float l = sax[i] + ajq;
          l = (l >= 0.f) ? l : 0.2f*l;
          mxv = fmaxf(mxv, l);
        }
      }
      float Z = 0.f;
      for (int i = 0; i < n; ++i){
        float s = 0.f;
        if (sAc[i*16 + tid] != 0.f){
          float l = sax[i] + ajq;
          l = (l >= 0.f) ? l : 0.2f*l;
          s = expf(l - mxv);
          Z += s;
        }
        sS[i*17 + tid] = s;
      }
      sInv[tid] = 1.f / Z;
    } else sInv[tid] = 0.f;
  }
  __syncthreads();

  for (int idx = tid; idx < n*16; idx += 256){
    int i = idx >> 4, jj = idx & 15;
    int j = j0 + jj;
    if (j < n) g_S[g*GS + i*128 + j] = sS[i*17 + jj] * sInv[jj];
  }
  int jt = tid >> 4, c0 = (tid & 15) * 8;
  float acc[8] = {0,0,0,0,0,0,0,0};
  for (int k = 0; k < n; ++k){
    float a = sS[k*17 + jt];
    if (a != 0.f) fma8(a, &sH[k*128 + c0], acc);
  }
  int j = j0 + jt;
  if (j < n){
    float inv = sInv[jt];
#pragma unroll
    for (int u = 0; u < 8; ++u) g_x2[g*GS + j*128 + c0 + u] = acc[u] * inv;
  }
}

__device__ void dv_fitk(float* sm, int g, int tid,
                        const float* __restrict__ le1w, const float* __restrict__ le1b,
                        const float* __restrict__ le2w, const float* __restrict__ le3w,
                        const float* __restrict__ le3b, int p, int n, int k)
{
  float* sa  = sm + 39328;
  float* sb  = sm + 39456;
  float* sfit= sm + 39584;
  int j = tid;
  if (j < 128){
    float av = 0.f, bv = 0.f;
    if (j < n){
      const float* X = g_x2 + g*GS + j*128;
      for (int c = 0; c < 128; ++c){
        float xv = __ldcg(X + c);
        av = fmaf(xv, __ldg(le1w + c), av);
        bv = fmaf(xv, __ldg(le2w + c), bv);
      }
      av += __ldg(le1b + p);
    }
    sa[j] = av; sb[j] = bv;
    sfit[j] = -3.4e38f;
  }
  __syncthreads();
  if (j < n){
    const float* X = g_x2 + g*GS + j*128;
    float c3 = 0.f;
    for (int c = 0; c < 128; ++c) c3 = fmaf(__ldcg(X + c), __ldg(le3w + c), c3);
    const float* Ab = g_A + g*GS;
    float s = 0.f, deg = 0.f;
    for (int i = 0; i < n; ++i){
      if (__ldcg(Ab + i*128 + j) != 0.f){ s += sa[i]; deg += 1.f; }
    }
    float f = s - deg*sb[j] + c3 + __ldg(le3b + p);
    float ff = 1.f / (1.f + expf(-f));
    sfit[j] = ff;
    g_fit[g*128 + j] = ff;
  }
  __syncthreads();
  if (j < 32){
    int lane = j;
    float v[4]; bool used[4];
#pragma unroll
    for (int s2 = 0; s2 < 4; ++s2){ v[s2] = sfit[lane + 32*s2]; used[s2] = false; }
    for (int r = 0; r < k; ++r){
      float bvv = -3.4e38f; int bi = 1 << 30;
#pragma unroll
      for (int s2 = 0; s2 < 4; ++s2){
        if (!used[s2]){
          int jj = lane + 32*s2;
          float xv = v[s2];
          if (xv > bvv || (xv == bvv && jj < bi)){ bvv = xv; bi = jj; }
        }
      }
#pragma unroll
      for (int off = 16; off; off >>= 1){
        float ov = __shfl_xor_sync(0xffffffffu, bvv, off);
        int   oi = __shfl_xor_sync(0xffffffffu, bi, off);
        if (ov > bvv || (ov == bvv && oi < bi)){ bvv = ov; bi = oi; }
      }
      if ((bi & 31) == lane) used[bi >> 5] = true;
      if (lane == 0) g_perm[g*128 + r] = bi;
    }
  }
}

__device__ void dv_aS(float* sm, int g, int r, int tid, float* __restrict__ houtg, int n, int k)
{
  float* sSel = sm;
  float* sAt  = sm + 34816;
  int*   sperm= (int*)(sm + 39712);
  int i0 = r*16;
  if (i0 >= n) return;
  if (tid < k) sperm[tid] = __ldcg(g_perm + g*128 + tid);
  __syncthreads();
  for (int idx = tid; idx < n*128; idx += 256){
    int m = idx >> 7, rr = idx & 127;
    sSel[idx] = (rr < k) ? __ldcg(g_S + g*GS + m*128 + sperm[rr]) : 0.f;
  }
  for (int idx = tid; idx < 16*128; idx += 256){
    int it = idx >> 7, m = idx & 127;
    sAt[m*17 + it] = __ldcg(g_A + g*GS + (i0+it)*128 + m);
  }
  __syncthreads();
  int it = tid >> 4, r0 = (tid & 15) * 8;
  float acc[8] = {0,0,0,0,0,0,0,0};
  for (int m = 0; m < n; ++m){
    float a = sAt[m*17 + it];
    if (a != 0.f) fma8(a, &sSel[m*128 + r0], acc);
  }
  int i = i0 + it;
  if (i < n){
#pragma unroll
    for (int u = 0; u < 8; ++u) g_T[g*GS + i*128 + r0 + u] = acc[u];
  }
  for (int idx = tid; idx < 16*128; idx += 256){
    int rt = idx >> 7, c = idx & 127;
    int rr = i0 + rt;
    if (rr < k){
      int pj = sperm[rr];
      houtg[rr*128 + c] = __ldcg(g_x2 + g*GS + pj*128 + c) * __ldcg(g_fit + g*128 + pj);
    }
  }
}

__device__ void dv_sTs(float* sm, int g, int r, int tid, int n, int k)
{
  float* sT  = sm;
  float* sSa = sm + 34816;
  int*   sperm= (int*)(sm + 39712);
  int r0 = r*16;
  if (r0 >= k) return;
  if (tid < k) sperm[tid] = __ldcg(g_perm + g*128 + tid);
  __syncthreads();
  {
    const float4* t4 = (const float4*)(g_T + g*GS);
    float4* s4 = (float4*)sT;
    for (int i4 = tid; i4 < n*32; i4 += 256) s4[i4] = __ldcg(t4 + i4);
  }
  for (int idx = tid; idx < n*16; idx += 256){
    int i = idx >> 4, rt2 = idx & 15;
    int rr = r0 + rt2;
    sSa[i*17 + rt2] = (rr < k) ? __ldcg(g_S + g*GS + i*128 + sperm[rr]) : 0.f;
  }
  __syncthreads();
  int rt = tid >> 4, c0 = (tid & 15) * 8;
  float acc[8] = {0,0,0,0,0,0,0,0};
  for (int i = 0; i < n; ++i){
    float a = sSa[i*17 + rt];
    if (a != 0.f) fma8(a, &sT[i*128 + c0], acc);
  }
  int rr = r0 + rt;
  if (rr < k){
#pragma unroll
    for (int u = 0; u < 8; ++u){
      int r2 = c0 + u;
      float v = (r2 == rr) ? 1.f : acc[u];
      g_A[g*GS + rr*128 + r2] = (r2 < k) ? v : 0.f;
    }
  }
}

__device__ void dv_head(float* sm, int g, int tid,
                        const float* __restrict__ b1, const float* __restrict__ w2,
                        const float* __restrict__ b2, float* __restrict__ out)
{
  float* sJ = sm;
  float* z1 = sm + 640;
  float* z2 = sm + 768;
  for (int c = tid; c < 640; c += 256) sJ[c] = __ldcg(g_xs + g*640 + c);
  __syncthreads();
  if (tid < 128){
    float s = __ldg(b1 + tid);
    for (int c = 0; c < 640; ++c) s = fmaf(sJ[c], g_w1t[c*128 + tid], s);
    z1[tid] = fmaxf(s, 0.f);
  }
  __syncthreads();
  if (tid < 2){
    float s2 = __ldg(b2 + tid);
    for (int c = 0; c < 128; ++c) s2 = fmaf(z1[c], __ldg(w2 + tid*128 + c), s2);
    z2[tid] = s2;
  }
  __syncthreads();
  if (tid == 0){
    float m = fmaxf(z2[0], z2[1]);
    float lse = m + logf(expf(z2[0] - m) + expf(z2[1] - m));
    out[g*2 + 0] = z2[0] - lse;
    out[g*2 + 1] = z2[1] - lse;
  }
}

// ---------------- the fused kernel (global-atomic group barriers) ----------------
__global__ void __launch_bounds__(256,1)
k_fused(const float* __restrict__ x, const int* __restrict__ ei, int E,
        const float* __restrict__ c0_brel, const float* __restrict__ cb_rel,
        const float* __restrict__ p_lin_b, const float* __restrict__ p_att_w,
        const float* __restrict__ p_att_b,
        const float* __restrict__ p_le1_w, const float* __restrict__ p_le1_b,
        const float* __restrict__ p_le2_w, const float* __restrict__ p_le3_w,
        const float* __restrict__ p_le3_b,
        const float* __restrict__ lin1_b, const float* __restrict__ lin2_w,
        const float* __restrict__ lin2_b, float* __restrict__ out)
{
  extern __shared__ float sm[];
  int g = blockIdx.x >> 3, r = blockIdx.x & 7, tid = threadIdx.x;
  float* hA = g_h  + g*GS;
  float* hB = g_hb + g*GS;
  int slot = 0;

  // S0: zero A block + xs, then scatter edges
  for (int i = r*256 + tid; i < GS; i += NCTA*256) g_A[g*GS + i] = 0.f;
  for (int i = r*256 + tid; i < 640; i += NCTA*256) g_xs[g*640 + i] = 0.f;
  gbar(g, slot++, tid);
  int Eg = E / NG;
  for (int e = g*Eg + r*256 + tid; e < (g+1)*Eg; e += NCTA*256){
    int u = ei[e], v = ei[E + e];
    atomicAdd(&g_A[g*GS + (u & 127)*128 + (v & 127)], 1.0f);
  }
  gbar(g, slot++, tid);

  // conv0 (64->128): x -> hA
  dv_conv(sm, g, r, tid, x + g*128*64, 64, hA, g_wt + 0*GS, g_wt + 1*GS, c0_brel, 0, 128, 64, 1.f/128.f);
  gbar(g, slot++, tid);
  // conv i=0: hA -> hB
  dv_conv(sm, g, r, tid, hA, 128, hB, g_wt + 2*GS, g_wt + 6*GS, cb_rel + 0, 1, 128, 128, 1.f/128.f);
  gbar(g, slot++, tid);

  // ---- pool 1 (128 -> 103), h=hB, x_out -> hA ----
  if (r == 0 && tid < 128) g_A[g*GS + tid*128 + tid] = 1.f;
  gbar(g, slot++, tid);
  dv_poolq(sm, g, r, tid, hB, g_wt + 10*GS, p_lin_b + 0, p_att_w + 0, 128);
  gbar(g, slot++, tid);
  dv_smaxx(sm, g, r, tid, hB, p_att_b, 0, 128);
  gbar(g, slot++, tid);
  if (r == 0) dv_fitk(sm, g, tid, p_le1_w + 0, p_le1_b, p_le2_w + 0, p_le3_w + 0, p_le3_b, 0, 128, 103);
  gbar(g, slot++, tid);
  dv_aS(sm, g, r, tid, hA, 128, 103);
  gbar(g, slot++, tid);
  dv_sTs(sm, g, r, tid, 128, 103);
  gbar(g, slot++, tid);

  // conv i=1: hA -> hB (n=103)
  dv_conv(sm, g, r, tid, hA, 128, hB, g_wt + 3*GS, g_wt + 7*GS, cb_rel + 128, 2, 103, 128, 1.f/103.f);
  gbar(g, slot++, tid);
  // conv i=2: hB -> hA
  dv_conv(sm, g, r, tid, hB, 128, hA, g_wt + 4*GS, g_wt + 8*GS, cb_rel + 256, 3, 103, 128, 1.f/103.f);
  gbar(g, slot++, tid);

  // ---- pool 2 (103 -> 83), h=hA, x_out -> hB ----
  dv_poolq(sm, g, r, tid, hA, g_wt + 11*GS, p_lin_b + 128, p_att_w + 256, 103);
  gbar(g, slot++, tid);
  dv_smaxx(sm, g, r, tid, hA, p_att_b, 1, 103);
  gbar(g, slot++, tid);
  if (r == 0) dv_fitk(sm, g, tid, p_le1_w + 128, p_le1_b, p_le2_w + 128, p_le3_w + 128, p_le3_b, 1, 103, 83);
  gbar(g, slot++, tid);
  dv_aS(sm, g, r, tid, hB, 103, 83);
  gbar(g, slot++, tid);
  dv_sTs(sm, g, r, tid, 103, 83);
  gbar(g, slot++, tid);

  // conv i=3: hB -> hA (n=83)
  dv_conv(sm, g, r, tid, hB, 128, hA, g_wt + 5*GS, g_wt + 9*GS, cb_rel + 384, 4, 83, 128, 1.f/83.f);
  gbar(g, slot++, tid);

  if (r == 0) dv_head(sm, g, tid, lin1_b, lin2_w, lin2_b, out);
}

// ---------------- host orchestration ----------------
extern "C" void kernel_launch(void* const* d_in, const int* in_sizes, int n_in,
                              void* d_out, int out_size)
{
  const float* x        = (const float*)d_in[0];
  const int*   ei       = (const int*)  d_in[1];
  const float* c0_wrel  = (const float*)d_in[2];
  const float* c0_brel  = (const float*)d_in[3];
  const float* c0_wroot = (const float*)d_in[4];
  const float* cw_rel   = (const float*)d_in[5];
  const float* cb_rel   = (const float*)d_in[6];
  const float* cw_root  = (const float*)d_in[7];
  const float* p_lin_w  = (const float*)d_in[8];
  const float* p_lin_b  = (const float*)d_in[9];
  const float* p_att_w  = (const float*)d_in[10];
  const float* p_att_b  = (const float*)d_in[11];
  const float* p_le1_w  = (const float*)d_in[12];
  const float* p_le1_b  = (const float*)d_in[13];
  const float* p_le2_w  = (const float*)d_in[14];
  const float* p_le3_w  = (const float*)d_in[15];
  const float* p_le3_b  = (const float*)d_in[16];
  const float* lin1_w   = (const float*)d_in[17];
  const float* lin1_b   = (const float*)d_in[18];
  const float* lin2_w   = (const float*)d_in[19];
  const float* lin2_b   = (const float*)d_in[20];

  static int inited = 0;
  const size_t SMB = (size_t)SMF * 4;
  if (!inited){
    cudaFuncSetAttribute(k_fused, cudaFuncAttributeMaxDynamicSharedMemorySize, (int)SMB);
    inited = 1;
  }

  int E = in_sizes[1] / 2;

  // prep covers 12*16384 + 640*128 + 512 elements -> 1091 blocks of 256
  k_prep<<<1091, 256>>>(c0_wrel, c0_wroot, cw_rel, cw_root, p_lin_w, lin1_w);
  k_fused<<<NG*NCTA, 256, SMB>>>(x, ei, E, c0_brel, cb_rel,
                                 p_lin_b, p_att_w, p_att_b,
                                 p_le1_w, p_le1_b, p_le2_w, p_le3_w, p_le3_b,
                                 lin1_b, lin2_w, lin2_b, (float*)d_out);
}

// round 6
// speedup vs baseline: 3.0552x; 1.5786x over previous
#include <cuda_runtime.h>
#include <math.h>

#define NG 16
#define GS 16384
#define NCTA 8
#define FULL 0xffffffffu

__device__ float g_A [NG*GS];
__device__ float g_h [NG*GS];
__device__ float g_hb[NG*GS];
__device__ float g_x2[NG*GS];
__device__ float g_S [NG*GS];
__device__ float g_T [NG*GS];
__device__ float g_B [NG*GS];
__device__ float g_wt[12*GS];
__device__ float g_w1t[640*128];
__device__ float g_xs[NG*640];
__device__ float g_fit[NG*128];
__device__ float g_ta[NG*128];   // aq
__device__ float g_tb[NG*128];   // ax
__device__ float g_fa[NG*128];   // fitness a
__device__ float g_fb[NG*128];   // fitness b
__device__ float g_fc[NG*128];   // fitness c3
__device__ int   g_perm[NG*128];
__device__ unsigned g_bar[NG*32];

// smem carve (floats)
#define O_H    0
#define O_W    16384
#define O_AC   49152
#define O_AG   51200   // 16*132
#define O_RED  53312   // 8*128
#define O_SA   54336   // 128
#define O_PERM 54464   // 128 ints
#define SMF    54592

__device__ __forceinline__ void gbar(int g,int slot,int tid){
  __syncthreads();
  if (tid==0){
    __threadfence();
    unsigned* p=&g_bar[g*32+slot];
    atomicAdd(p,1u);
    unsigned v;
    do{ asm volatile("ld.acquire.gpu.u32 %0,[%1];":"=r"(v):"l"(p):"memory"); }while(v<NCTA);
  }
  __syncthreads();
}
__device__ __forceinline__ float wsum(float v){
#pragma unroll
  for(int o=16;o;o>>=1) v+=__shfl_xor_sync(FULL,v,o);
  return v;
}
__device__ __forceinline__ float wmax(float v){
#pragma unroll
  for(int o=16;o;o>>=1) v=fmaxf(v,__shfl_xor_sync(FULL,v,o));
  return v;
}
__device__ __forceinline__ void fma4(float4&o,float a,const float4 w){
  o.x=fmaf(a,w.x,o.x);o.y=fmaf(a,w.y,o.y);o.z=fmaf(a,w.z,o.z);o.w=fmaf(a,w.w,o.w);
}
__device__ __forceinline__ float dot4(const float4 a,const float4 b){
  return a.x*b.x+a.y*b.y+a.z*b.z+a.w*b.w;
}

// ---------------- prep ----------------
__global__ void k_prep(const float* __restrict__ c0r,const float* __restrict__ c0t,
                       const float* __restrict__ cwr,const float* __restrict__ cwt,
                       const float* __restrict__ plw,const float* __restrict__ w1){
  int idx=blockIdx.x*256+threadIdx.x;
  if(idx<12*GS){
    int slot=idx>>14,e=idx&16383,c=e>>7,o=e&127;
    const float* src;int Cin;
    if(slot==0){src=c0r;Cin=64;}
    else if(slot==1){src=c0t;Cin=64;}
    else if(slot<6){src=cwr+(slot-2)*GS;Cin=128;}
    else if(slot<10){src=cwt+(slot-6)*GS;Cin=128;}
    else{src=plw+(slot-10)*GS;Cin=128;}
    g_wt[idx]=(c<Cin)?src[o*Cin+c]:0.f;
  }else if(idx<12*GS+640*128){
    int j=idx-12*GS,c=j>>7,o=j&127;
    g_w1t[j]=w1[o*640+c];
  }else if(idx<12*GS+640*128+NG*32){
    g_bar[idx-12*GS-640*128]=0u;
  }
}

// ---------------- conv ----------------
__device__ void dv_conv(float* sm,int g,int r,int tid,const float* __restrict__ X,int Cin,
                        float* __restrict__ hout,const float* __restrict__ wt1,
                        const float* __restrict__ wt2,const float* __restrict__ brel,
                        int slot,int n,float invn){
  float* sH=sm+O_H; float* sW=sm+O_W; float* sAc=sm+O_AC; float* sAg=sm+O_AG; float* sRed=sm+O_RED;
  int lane=tid&31,w=tid>>5,c0=lane*4;
  int j0=r*16,jr0=2*w,jr1=jr0+1,jA=j0+jr0,jB=j0+jr1;
  const float* Ab=g_A+g*GS;
  if(Cin==128&&n==128){
    for(int i4=tid;i4<4096;i4+=256) ((float4*)sH)[i4]=__ldcg((const float4*)X+i4);
  }else{
    for(int idx=tid;idx<16384;idx+=256){
      int i=idx>>7,c=idx&127;
      float v=0.f;
      if(i<n&&c<Cin) v=(Cin==128)?__ldcg(X+i*128+c):__ldg(X+i*64+c);
      sH[idx]=v;
    }
  }
  for(int idx=tid;idx<2048;idx+=256){
    int i=idx>>4,jr=idx&15,j=j0+jr;
    sAc[idx]=(i<n&&j<n)?__ldcg(Ab+i*128+j):0.f;
  }
  for(int i4=tid;i4<4096;i4+=256) ((float4*)sW)[i4]=__ldg((const float4*)wt1+i4);
  for(int i4=tid;i4<4096;i4+=256) ((float4*)(sW+16384))[i4]=__ldg((const float4*)wt2+i4);
  __syncthreads();
  // deg
  float cd0=0.f,cd1=0.f;
  for(int i=lane;i<n;i+=32){
    float2 a=*(const float2*)&sAc[i*16+jr0];
    cd0+=(a.x!=0.f)?1.f:0.f; cd1+=(a.y!=0.f)?1.f:0.f;
  }
  cd0=wsum(cd0); cd1=wsum(cd1);
  float id0=1.f/fmaxf(cd0,1.f), id1=1.f/fmaxf(cd1,1.f);
  // phase1: agg rows
  float4 A0={0,0,0,0},A1={0,0,0,0};
  for(int i=0;i<n;++i){
    float2 av=*(const float2*)&sAc[i*16+jr0];
    if(av.x!=0.f||av.y!=0.f){
      float4 hv=*(const float4*)&sH[i*128+c0];
      fma4(A0,av.x,hv); fma4(A1,av.y,hv);
    }
  }
  A0.x*=id0;A0.y*=id0;A0.z*=id0;A0.w*=id0;
  A1.x*=id1;A1.y*=id1;A1.z*=id1;A1.w*=id1;
  *(float4*)&sAg[jr0*132+c0]=A0; *(float4*)&sAg[jr1*132+c0]=A1;
  __syncthreads();
  // dense: out = agg@W1 + h@W2
  int ja=(jA<n)?jA:0,jb=(jB<n)?jB:0;
  const float* g0=&sAg[jr0*132]; const float* g1=&sAg[jr1*132];
  const float* h0p=&sH[ja*128]; const float* h1p=&sH[jb*128];
  float4 O0={0,0,0,0},O1={0,0,0,0};
#pragma unroll 4
  for(int k=0;k<128;++k){
    float a0=g0[k],a1=g1[k],h0=h0p[k],h1=h1p[k];
    float4 w1=*(const float4*)&sW[k*128+c0];
    float4 w2=*(const float4*)&sW[16384+k*128+c0];
    fma4(O0,a0,w1); fma4(O0,h0,w2);
    fma4(O1,a1,w1); fma4(O1,h1,w2);
  }
  float4 bb=__ldg((const float4*)(brel+c0));
  float4 V0,V1;
  V0.x=fmaxf(O0.x+bb.x,0.f);V0.y=fmaxf(O0.y+bb.y,0.f);V0.z=fmaxf(O0.z+bb.z,0.f);V0.w=fmaxf(O0.w+bb.w,0.f);
  V1.x=fmaxf(O1.x+bb.x,0.f);V1.y=fmaxf(O1.y+bb.y,0.f);V1.z=fmaxf(O1.z+bb.z,0.f);V1.w=fmaxf(O1.w+bb.w,0.f);
  if(jA<n) *(float4*)&hout[jA*128+c0]=V0; else V0=make_float4(0,0,0,0);
  if(jB<n) *(float4*)&hout[jB*128+c0]=V1; else V1=make_float4(0,0,0,0);
  float4 P; P.x=V0.x+V1.x;P.y=V0.y+V1.y;P.z=V0.z+V1.z;P.w=V0.w+V1.w;
  *(float4*)&sRed[w*128+c0]=P;
  __syncthreads();
  if(tid<128){
    float s=0.f;
#pragma unroll
    for(int q=0;q<8;++q) s+=sRed[q*128+tid];
    atomicAdd(&g_xs[g*640+slot*128+tid],s*invn);
  }
}

// ---------------- poolq ----------------
__device__ void dv_poolq(float* sm,int g,int r,int tid,const float* __restrict__ hg,
                         const float* __restrict__ wt,const float* __restrict__ linb,
                         const float* __restrict__ attw,int n){
  float* sH=sm+O_H; float* sW=sm+O_W; float* sAc=sm+O_AC; float* sAg=sm+O_AG;
  int lane=tid&31,w=tid>>5,c0=lane*4;
  int j0=r*16,jr0=2*w,jr1=jr0+1,jA=j0+jr0,jB=j0+jr1;
  const float* Ab=g_A+g*GS;
  for(int idx=tid;idx<16384;idx+=256){
    int i=idx>>7;
    sH[idx]=(i<n)?__ldcg(hg+idx):0.f;
  }
  for(int idx=tid;idx<2048;idx+=256){
    int i=idx>>4,jr=idx&15,j=j0+jr;
    sAc[idx]=(i<n&&j<n)?__ldcg(Ab+i*128+j):0.f;
  }
  for(int i4=tid;i4<4096;i4+=256) ((float4*)sW)[i4]=__ldg((const float4*)wt+i4);
  __syncthreads();
  float4 M0=make_float4(-1e30f,-1e30f,-1e30f,-1e30f),M1=M0;
  for(int i=0;i<n;++i){
    float2 av=*(const float2*)&sAc[i*16+jr0];
    bool m0=(av.x!=0.f)||(i==jA), m1=(av.y!=0.f)||(i==jB);
    if(m0||m1){
      float4 hv=*(const float4*)&sH[i*128+c0];
      if(m0){M0.x=fmaxf(M0.x,hv.x);M0.y=fmaxf(M0.y,hv.y);M0.z=fmaxf(M0.z,hv.z);M0.w=fmaxf(M0.w,hv.w);}
      if(m1){M1.x=fmaxf(M1.x,hv.x);M1.y=fmaxf(M1.y,hv.y);M1.z=fmaxf(M1.z,hv.z);M1.w=fmaxf(M1.w,hv.w);}
    }
  }
  *(float4*)&sAg[jr0*132+c0]=M0; *(float4*)&sAg[jr1*132+c0]=M1;
  __syncthreads();
  const float* q0=&sAg[jr0*132]; const float* q1=&sAg[jr1*132];
  float4 Q0={0,0,0,0},Q1={0,0,0,0};
#pragma unroll 4
  for(int k=0;k<128;++k){
    float a0=q0[k],a1=q1[k];
    float4 wv=*(const float4*)&sW[k*128+c0];
    fma4(Q0,a0,wv); fma4(Q1,a1,wv);
  }
  float4 lb=__ldg((const float4*)(linb+c0));
  Q0.x+=lb.x;Q0.y+=lb.y;Q0.z+=lb.z;Q0.w+=lb.w;
  Q1.x+=lb.x;Q1.y+=lb.y;Q1.z+=lb.z;Q1.w+=lb.w;
  float4 awq=__ldg((const float4*)(attw+c0));
  float4 awx=__ldg((const float4*)(attw+128+c0));
  int ja=(jA<n)?jA:0,jb=(jB<n)?jB:0;
  float4 h0=*(const float4*)&sH[ja*128+c0], h1=*(const float4*)&sH[jb*128+c0];
  float p0=wsum(dot4(Q0,awq)), p1=wsum(dot4(Q1,awq));
  float x0=wsum(dot4(h0,awx)), x1=wsum(dot4(h1,awx));
  if(lane==0){
    if(jA<n){g_ta[g*128+jA]=p0; g_tb[g*128+jA]=x0;}
    if(jB<n){g_ta[g*128+jB]=p1; g_tb[g*128+jB]=x1;}
  }
}

// ---------------- smaxx + fitness-prep ----------------
__device__ void dv_smaxx(float* sm,int g,int r,int tid,const float* __restrict__ hg,
                         const float* __restrict__ attbp,
                         const float* __restrict__ le1w,const float* __restrict__ le1bp,
                         const float* __restrict__ le2w,const float* __restrict__ le3w,int n){
  float* sH=sm+O_H; float* sAc=sm+O_AC; float* sAg=sm+O_AG; float* sax=sm+O_SA;
  int lane=tid&31,w=tid>>5,c0=lane*4;
  int j0=r*16,jr0=2*w,jr1=jr0+1,jA=j0+jr0,jB=j0+jr1;
  const float* Ab=g_A+g*GS;
  for(int idx=tid;idx<16384;idx+=256){
    int i=idx>>7;
    sH[idx]=(i<n)?__ldcg(hg+idx):0.f;
  }
  for(int idx=tid;idx<2048;idx+=256){
    int i=idx>>4,jr=idx&15,j=j0+jr;
    sAc[idx]=(i<n&&j<n)?__ldcg(Ab+i*128+j):0.f;
  }
  if(tid<128) sax[tid]=(tid<n)?__ldcg(g_tb+g*128+tid):0.f;
  __syncthreads();
  float attb=__ldg(attbp);
  float aq0=((jA<n)?__ldcg(g_ta+g*128+jA):0.f)+attb;
  float aq1=((jB<n)?__ldcg(g_ta+g*128+jB):0.f)+attb;
  float l0[4],l1[4]; int m0[4],m1[4];
  float mx0=-1e30f,mx1=-1e30f;
#pragma unroll
  for(int u=0;u<4;++u){
    int i=lane+32*u;
    float2 av=*(const float2*)&sAc[i*16+jr0];
    int b0=(i<n)&&(jA<n)&&((av.x!=0.f)||(i==jA));
    int b1=(i<n)&&(jB<n)&&((av.y!=0.f)||(i==jB));
    float ax=sax[i];
    float t0=ax+aq0; t0=(t0>=0.f)?t0:0.2f*t0;
    float t1=ax+aq1; t1=(t1>=0.f)?t1:0.2f*t1;
    l0[u]=b0?t0:-1e30f; m0[u]=b0; mx0=fmaxf(mx0,l0[u]);
    l1[u]=b1?t1:-1e30f; m1[u]=b1; mx1=fmaxf(mx1,l1[u]);
  }
  mx0=wmax(mx0); mx1=wmax(mx1);
  float Z0=0.f,Z1=0.f; float s0[4],s1[4];
#pragma unroll
  for(int u=0;u<4;++u){
    s0[u]=m0[u]?expf(l0[u]-mx0):0.f; Z0+=s0[u];
    s1[u]=m1[u]?expf(l1[u]-mx1):0.f; Z1+=s1[u];
  }
  Z0=wsum(Z0); Z1=wsum(Z1);
  float iz0=(jA<n)?1.f/Z0:0.f, iz1=(jB<n)?1.f/Z1:0.f;
#pragma unroll
  for(int u=0;u<4;++u){
    int i=lane+32*u;
    float v0=s0[u]*iz0, v1=s1[u]*iz1;
    sAg[jr0*132+i]=v0; sAg[jr1*132+i]=v1;
    if(i<n){
      if(jA<n) g_S[g*GS+i*128+jA]=v0;
      if(jB<n) g_S[g*GS+i*128+jB]=v1;
    }
  }
  __syncwarp();
  float4 O0={0,0,0,0},O1={0,0,0,0};
  for(int i=0;i<n;++i){
    float t0=sAg[jr0*132+i], t1=sAg[jr1*132+i];
    if(t0!=0.f||t1!=0.f){
      float4 hv=*(const float4*)&sH[i*128+c0];
      fma4(O0,t0,hv); fma4(O1,t1,hv);
    }
  }
  if(jA<n) *(float4*)&g_x2[g*GS+jA*128+c0]=O0;
  if(jB<n) *(float4*)&g_x2[g*GS+jB*128+c0]=O1;
  // fitness prep
  float4 w1v=__ldg((const float4*)(le1w+c0));
  float4 w2v=__ldg((const float4*)(le2w+c0));
  float4 w3v=__ldg((const float4*)(le3w+c0));
  float a0=wsum(dot4(O0,w1v)), b0=wsum(dot4(O0,w2v)), cc0=wsum(dot4(O0,w3v));
  float a1=wsum(dot4(O1,w1v)), b1=wsum(dot4(O1,w2v)), cc1=wsum(dot4(O1,w3v));
  if(lane==0){
    float l1b=__ldg(le1bp);
    if(jA<n){g_fa[g*128+jA]=a0+l1b; g_fb[g*128+jA]=b0; g_fc[g*128+jA]=cc0;}
    if(jB<n){g_fa[g*128+jB]=a1+l1b; g_fb[g*128+jB]=b1; g_fc[g*128+jB]=cc1;}
  }
}

// ---------------- T = A_diag @ S  +  fitness finalize ----------------
__device__ void dv_fitT(float* sm,int g,int r,int tid,const float* __restrict__ le3bp,int n){
  float* sS=sm+O_H; float* sAr=sm+O_W; float* sAc=sm+O_AC; float* sa=sm+O_SA;
  int lane=tid&31,w=tid>>5,c0=lane*4;
  int j0=r*16,jr0=2*w,jr1=jr0+1,jA=j0+jr0,jB=j0+jr1;
  const float* Ab=g_A+g*GS;
  for(int idx=tid;idx<16384;idx+=256){
    int i=idx>>7;
    sS[idx]=(i<n)?__ldcg(g_S+g*GS+idx):0.f;
  }
  for(int idx=tid;idx<2048;idx+=256){
    int it=idx>>7,m=idx&127,i=j0+it;
    float v=(i<n&&m<n)?__ldcg(Ab+i*128+m):0.f;
    if(m==i&&i<n) v=1.f;
    sAr[it*132+m]=v;
  }
  for(int idx=tid;idx<2048;idx+=256){
    int i=idx>>4,jr=idx&15,j=j0+jr;
    sAc[idx]=(i<n&&j<n)?__ldcg(Ab+i*128+j):0.f;
  }
  if(tid<128) sa[tid]=(tid<n)?__ldcg(g_fa+g*128+tid):0.f;
  __syncthreads();
  const float* a0p=&sAr[jr0*132]; const float* a1p=&sAr[jr1*132];
  float4 T0={0,0,0,0},T1={0,0,0,0};
  for(int m=0;m<n;++m){
    float a0=a0p[m],a1=a1p[m];
    if(a0!=0.f||a1!=0.f){
      float4 sv=*(const float4*)&sS[m*128+c0];
      fma4(T0,a0,sv); fma4(T1,a1,sv);
    }
  }
  if(jA<n) *(float4*)&g_T[g*GS+jA*128+c0]=T0;
  if(jB<n) *(float4*)&g_T[g*GS+jB*128+c0]=T1;
  // fitness: s = sum_i mask(i,j)*a[i], deg
  float s0=0.f,s1=0.f,d0=0.f,d1=0.f;
  for(int i=lane;i<n;i+=32){
    float2 av=*(const float2*)&sAc[i*16+jr0];
    if((av.x!=0.f)||(i==jA)){s0+=sa[i];d0+=1.f;}
    if((av.y!=0.f)||(i==jB)){s1+=sa[i];d1+=1.f;}
  }
  s0=wsum(s0);d0=wsum(d0);s1=wsum(s1);d1=wsum(d1);
  if(lane==0){
    float l3b=__ldg(le3bp);
    if(jA<n){
      float f=s0-d0*__ldcg(g_fb+g*128+jA)+__ldcg(g_fc+g*128+jA)+l3b;
      g_fit[g*128+jA]=1.f/(1.f+expf(-f));
    }
    if(jB<n){
      float f=s1-d1*__ldcg(g_fb+g*128+jB)+__ldcg(g_fc+g*128+jB)+l3b;
      g_fit[g*128+jB]=1.f/(1.f+expf(-f));
    }
  }
}

// ---------------- B = S^T @ T  +  top-k ----------------
__device__ void dv_B(float* sm,int g,int r,int tid,int n,int k){
  float* sT=sm+O_H; float* sSc=sm+O_AC;
  int lane=tid&31,w=tid>>5,c0=lane*4;
  int j0=r*16,jr0=2*w,jr1=jr0+1,jA=j0+jr0,jB=j0+jr1;
  for(int idx=tid;idx<16384;idx+=256){
    int i=idx>>7;
    sT[idx]=(i<n)?__ldcg(g_T+g*GS+idx):0.f;
  }
  for(int idx=tid;idx<2048;idx+=256){
    int i=idx>>4,jr=idx&15,j=j0+jr;
    sSc[idx]=(i<n&&j<n)?__ldcg(g_S+g*GS+i*128+j):0.f;
  }
  __syncthreads();
  float4 B0={0,0,0,0},B1={0,0,0,0};
  for(int i=0;i<n;++i){
    float2 sv=*(const float2*)&sSc[i*16+jr0];
    if(sv.x!=0.f||sv.y!=0.f){
      float4 tv=*(const float4*)&sT[i*128+c0];
      fma4(B0,sv.x,tv); fma4(B1,sv.y,tv);
    }
  }
  if(jA<n) *(float4*)&g_B[g*GS+jA*128+c0]=B0;
  if(jB<n) *(float4*)&g_B[g*GS+jB*128+c0]=B1;
  // top-k on r==0 warp 0 (fitness already globally visible via prior gbar)
  if(r==0&&w==0){
    float v[4]; bool used[4];
#pragma unroll
    for(int u=0;u<4;++u){
      int jj=lane+32*u;
      v[u]=(jj<n)?__ldcg(g_fit+g*128+jj):-3.4e38f;
      used[u]=false;
    }
    for(int rr=0;rr<k;++rr){
      float bv=-3.4e38f; int bi=1<<30;
#pragma unroll
      for(int u=0;u<4;++u){
        if(!used[u]){
          int jj=lane+32*u;
          if(v[u]>bv||(v[u]==bv&&jj<bi)){bv=v[u];bi=jj;}
        }
      }
#pragma unroll
      for(int o=16;o;o>>=1){
        float ov=__shfl_xor_sync(FULL,bv,o);
        int oi=__shfl_xor_sync(FULL,bi,o);
        if(ov>bv||(ov==bv&&oi<bi)){bv=ov;bi=oi;}
      }
      if((bi&31)==lane) used[bi>>5]=true;
      if(lane==0) g_perm[g*128+rr]=bi;
    }
  }
}

// ---------------- gather: A2 + x_out ----------------
__device__ void dv_gather(float* sm,int g,int r,int tid,float* __restrict__ hout,int n,int k){
  int* sp=(int*)(sm+O_PERM);
  if(tid<128) sp[tid]=(tid<k)?__ldcg(g_perm+g*128+tid):0;
  __syncthreads();
  int i0=r*16;
  for(int idx=tid;idx<2048;idx+=256){
    int rt=idx>>7,c=idx&127,rr=i0+rt;
    if(rr<k){
      int pj=sp[rr];
      float fv=__ldcg(g_fit+g*128+pj);
      float a2=0.f;
      if(c<k) a2=(c==rr)?1.f:__ldcg(g_B+g*GS+pj*128+sp[c]);
      g_A[g*GS+rr*128+c]=a2;
      hout[rr*128+c]=__ldcg(g_x2+g*GS+pj*128+c)*fv;
    }
  }
}

// ---------------- head ----------------
__device__ void dv_head(float* sm,int g,int tid,const float* __restrict__ b1,
                        const float* __restrict__ w2,const float* __restrict__ b2,
                        float* __restrict__ out){
  float* sJ=sm+O_H; float* z1=sm+O_H+704; float* z2=sm+O_H+840;
  for(int c=tid;c<640;c+=256) sJ[c]=__ldcg(g_xs+g*640+c);
  __syncthreads();
  if(tid<128){
    float s=__ldg(b1+tid);
    for(int c=0;c<640;++c) s=fmaf(sJ[c],g_w1t[c*128+tid],s);
    z1[tid]=fmaxf(s,0.f);
  }
  __syncthreads();
  if(tid<2){
    float s2=__ldg(b2+tid);
    for(int c=0;c<128;++c) s2=fmaf(z1[c],__ldg(w2+tid*128+c),s2);
    z2[tid]=s2;
  }
  __syncthreads();
  if(tid==0){
    float m=fmaxf(z2[0],z2[1]);
    float lse=m+logf(expf(z2[0]-m)+expf(z2[1]-m));
    out[g*2+0]=z2[0]-lse;
    out[g*2+1]=z2[1]-lse;
  }
}

// ---------------- fused kernel ----------------
__global__ void __launch_bounds__(256,1)
k_fused(const float* __restrict__ x,const int* __restrict__ ei,int E,
        const float* __restrict__ c0_brel,const float* __restrict__ cb_rel,
        const float* __restrict__ p_lin_b,const float* __restrict__ p_att_w,
        const float* __restrict__ p_att_b,
        const float* __restrict__ p_le1_w,const float* __restrict__ p_le1_b,
        const float* __restrict__ p_le2_w,const float* __restrict__ p_le3_w,
        const float* __restrict__ p_le3_b,
        const float* __restrict__ lin1_b,const float* __restrict__ lin2_w,
        const float* __restrict__ lin2_b,float* __restrict__ out){
  extern __shared__ float sm[];
  int g=blockIdx.x>>3,r=blockIdx.x&7,tid=threadIdx.x;
  float* hA=g_h+g*GS;
  float* hB=g_hb+g*GS;
  int sl=0;
  int j0=r*16;
  // init: zero own A rows + xs, write own edges (race-free)
  for(int idx=tid;idx<2048;idx+=256) g_A[g*GS+(j0+(idx>>7))*128+(idx&127)]=0.f;
  if(r==0) for(int i=tid;i<640;i+=256) g_xs[g*640+i]=0.f;
  __syncthreads();
  {
    int e=(g*128+j0)*16+tid;  // 256 edges per CTA
    int u=__ldg(ei+e),v=__ldg(ei+E+e);
    g_A[g*GS+(u&127)*128+(v&127)]=1.f;
  }
  gbar(g,sl++,tid);

  dv_conv(sm,g,r,tid,x+g*128*64,64,hA,g_wt+0*GS,g_wt+1*GS,c0_brel,0,128,1.f/128.f);
  gbar(g,sl++,tid);
  dv_conv(sm,g,r,tid,hA,128,hB,g_wt+2*GS,g_wt+6*GS,cb_rel+0,1,128,1.f/128.f);
  gbar(g,sl++,tid);

  // pool 1: n=128 -> k=103, h=hB, x_out -> hA
  dv_poolq(sm,g,r,tid,hB,g_wt+10*GS,p_lin_b+0,p_att_w+0,128);
  gbar(g,sl++,tid);
  dv_smaxx(sm,g,r,tid,hB,p_att_b+0,p_le1_w+0,p_le1_b+0,p_le2_w+0,p_le3_w+0,128);
  gbar(g,sl++,tid);
  dv_fitT(sm,g,r,tid,p_le3_b+0,128);
  gbar(g,sl++,tid);
  dv_B(sm,g,r,tid,128,103);
  gbar(g,sl++,tid);
  dv_gather(sm,g,r,tid,hA,128,103);
  gbar(g,sl++,tid);

  dv_conv(sm,g,r,tid,hA,128,hB,g_wt+3*GS,g_wt+7*GS,cb_rel+128,2,103,1.f/103.f);
  gbar(g,sl++,tid);
  dv_conv(sm,g,r,tid,hB,128,hA,g_wt+4*GS,g_wt+8*GS,cb_rel+256,3,103,1.f/103.f);
  gbar(g,sl++,tid);

  // pool 2: n=103 -> k=83, h=hA, x_out -> hB
  dv_poolq(sm,g,r,tid,hA,g_wt+11*GS,p_lin_b+128,p_att_w+256,103);
  gbar(g,sl++,tid);
  dv_smaxx(sm,g,r,tid,hA,p_att_b+1,p_le1_w+128,p_le1_b+1,p_le2_w+128,p_le3_w+128,103);
  gbar(g,sl++,tid);
  dv_fitT(sm,g,r,tid,p_le3_b+1,103);
  gbar(g,sl++,tid);
  dv_B(sm,g,r,tid,103,83);
  gbar(g,sl++,tid);
  dv_gather(sm,g,r,tid,hB,103,83);
  gbar(g,sl++,tid);

  dv_conv(sm,g,r,tid,hB,128,hA,g_wt+5*GS,g_wt+9*GS,cb_rel+384,4,83,1.f/83.f);
  gbar(g,sl++,tid);

  if(r==0) dv_head(sm,g,tid,lin1_b,lin2_w,lin2_b,out);
}

// ---------------- host ----------------
extern "C" void kernel_launch(void* const* d_in,const int* in_sizes,int n_in,
                              void* d_out,int out_size){
  const float* x       =(const float*)d_in[0];
  const int*   ei      =(const int*)  d_in[1];
  const float* c0_wrel =(const float*)d_in[2];
  const float* c0_brel =(const float*)d_in[3];
  const float* c0_wroot=(const float*)d_in[4];
  const float* cw_rel  =(const float*)d_in[5];
  const float* cb_rel  =(const float*)d_in[6];
  const float* cw_root =(const float*)d_in[7];
  const float* p_lin_w =(const float*)d_in[8];
  const float* p_lin_b =(const float*)d_in[9];
  const float* p_att_w =(const float*)d_in[10];
  const float* p_att_b =(const float*)d_in[11];
  const float* p_le1_w =(const float*)d_in[12];
  const float* p_le1_b =(const float*)d_in[13];
  const float* p_le2_w =(const float*)d_in[14];
  const float* p_le3_w =(const float*)d_in[15];
  const float* p_le3_b =(const float*)d_in[16];
  const float* lin1_w  =(const float*)d_in[17];
  const float* lin1_b  =(const float*)d_in[18];
  const float* lin2_w  =(const float*)d_in[19];
  const float* lin2_b  =(const float*)d_in[20];

  static int inited=0;
  const size_t SMB=(size_t)SMF*4;
  if(!inited){
    cudaFuncSetAttribute(k_fused,cudaFuncAttributeMaxDynamicSharedMemorySize,(int)SMB);
    inited=1;
  }
  int E=in_sizes[1]/2;
  k_prep<<<1090,256>>>(c0_wrel,c0_wroot,cw_rel,cw_root,p_lin_w,lin1_w);
  k_fused<<<NG*NCTA,256,SMB>>>(x,ei,E,c0_brel,cb_rel,
                               p_lin_b,p_att_w,p_att_b,
                               p_le1_w,p_le1_b,p_le2_w,p_le3_w,p_le3_b,
                               lin1_b,lin2_w,lin2_b,(float*)d_out);
}

// round 7
// speedup vs baseline: 3.8451x; 1.2586x over previous
#include <cuda_runtime.h>
#include <math.h>

#define NG 16
#define GS 16384
#define NCTA 8
#define NT 512
#define FULL 0xffffffffu

__device__ float g_A [NG*GS];
__device__ float g_h [NG*GS];
__device__ float g_hb[NG*GS];
__device__ float g_x2[NG*GS];
__device__ float g_S [NG*GS];
__device__ float g_T [NG*GS];
__device__ float g_B [NG*GS];
__device__ float g_wt[12*GS];
__device__ float g_w1t[640*128];
__device__ float g_xs[NG*640];
__device__ float g_fit[NG*128];
__device__ float g_fa[NG*128];
__device__ float g_fb[NG*128];
__device__ float g_fc[NG*128];
__device__ int   g_perm[NG*128];
__device__ unsigned g_bar[NG*32];

// smem carve (floats)
#define O_H    0        // 16384
#define O_W    16384    // 32768 (W1 @ +0, W2 @ +16384)
#define O_AC   49152    // 2048 (A cols / dense partials)
#define O_AG   51200    // 2112 (16 x 132)
#define O_RED  53312    // 1024 (gpool partials 8x128)
#define O_SA   54336    // 128
#define O_DEG  54464    // 32
#define O_PERM 54496    // 128 ints
#define SMF    54624

__device__ __forceinline__ void gbar(int g,int slot,int tid){
  __syncthreads();
  if (tid==0){
    __threadfence();
    unsigned* p=&g_bar[g*32+slot];
    atomicAdd(p,1u);
    unsigned v;
    do{ asm volatile("ld.acquire.gpu.u32 %0,[%1];":"=r"(v):"l"(p):"memory"); }while(v<NCTA);
  }
  __syncthreads();
}
__device__ __forceinline__ float wsum(float v){
#pragma unroll
  for(int o=16;o;o>>=1) v+=__shfl_xor_sync(FULL,v,o);
  return v;
}
__device__ __forceinline__ float wmax(float v){
#pragma unroll
  for(int o=16;o;o>>=1) v=fmaxf(v,__shfl_xor_sync(FULL,v,o));
  return v;
}
__device__ __forceinline__ void fma4(float4&o,float a,const float4 w){
  o.x=fmaf(a,w.x,o.x);o.y=fmaf(a,w.y,o.y);o.z=fmaf(a,w.z,o.z);o.w=fmaf(a,w.w,o.w);
}
__device__ __forceinline__ float dot4(const float4 a,const float4 b){
  return a.x*b.x+a.y*b.y+a.z*b.z+a.w*b.w;
}

// ---------------- prep ----------------
__global__ void k_prep(const float* __restrict__ c0r,const float* __restrict__ c0t,
                       const float* __restrict__ cwr,const float* __restrict__ cwt,
                       const float* __restrict__ plw,const float* __restrict__ w1){
  int idx=blockIdx.x*256+threadIdx.x;
  if(idx<12*GS){
    int slot=idx>>14,e=idx&16383,c=e>>7,o=e&127;
    const float* src;int Cin;
    if(slot==0){src=c0r;Cin=64;}
    else if(slot==1){src=c0t;Cin=64;}
    else if(slot<6){src=cwr+(slot-2)*GS;Cin=128;}
    else if(slot<10){src=cwt+(slot-6)*GS;Cin=128;}
    else{src=plw+(slot-10)*GS;Cin=128;}
    g_wt[idx]=(c<Cin)?src[o*Cin+c]:0.f;
  }else if(idx<12*GS+640*128){
    int j=idx-12*GS,c=j>>7,o=j&127;
    g_w1t[j]=w1[o*640+c];
  }else if(idx<12*GS+640*128+NG*32){
    g_bar[idx-12*GS-640*128]=0u;
  }
}

// ---------------- conv ----------------
__device__ void dv_conv(float* sm,int g,int r,int tid,const float* __restrict__ X,int Cin,
                        float* __restrict__ hout,const float* __restrict__ wt1,
                        const float* __restrict__ wt2,const float* __restrict__ brel,
                        int slot,int n,float invn){
  float* sH=sm+O_H; float* sW=sm+O_W; float* sAc=sm+O_AC; float* sAg=sm+O_AG;
  float* sRed=sm+O_RED; float* sDeg=sm+O_DEG;
  int lane=tid&31,w=tid>>5,c0=lane*4;
  int p=w&7,hf=w>>3;
  int j0=r*16,jr0=2*p,jr1=jr0+1,jA=j0+jr0,jB=j0+jr1;
  const float* Ab=g_A+g*GS;

  if(Cin==128&&n==128){
    for(int i4=tid;i4<4096;i4+=NT) ((float4*)sH)[i4]=__ldcg((const float4*)X+i4);
  }else{
    for(int idx=tid;idx<16384;idx+=NT){
      int i=idx>>7,c=idx&127;
      float v=0.f;
      if(i<n&&c<Cin) v=(Cin==128)?__ldcg(X+i*128+c):__ldg(X+i*64+c);
      sH[idx]=v;
    }
  }
  for(int idx=tid;idx<2048;idx+=NT){
    int i=idx>>4,jr=idx&15,j=j0+jr;
    sAc[idx]=(i<n&&j<n)?__ldcg(Ab+i*128+j):0.f;
  }
  for(int i4=tid;i4<4096;i4+=NT) ((float4*)sW)[i4]=__ldg((const float4*)wt1+i4);
  for(int i4=tid;i4<4096;i4+=NT) ((float4*)(sW+16384))[i4]=__ldg((const float4*)wt2+i4);
  __syncthreads();

  // phase1: agg partials over i-half
  int ilo=hf*64, ihi=min(n,hf*64+64);
  float4 A0={0,0,0,0},A1={0,0,0,0};
  for(int i=ilo;i<ihi;++i){
    float2 av=*(const float2*)&sAc[i*16+jr0];
    if(av.x!=0.f||av.y!=0.f){
      float4 hv=*(const float4*)&sH[i*128+c0];
      fma4(A0,av.x,hv); fma4(A1,av.y,hv);
    }
  }
  float cd0=0.f,cd1=0.f;
  for(int i=ilo+lane;i<ihi;i+=32){
    float2 a=*(const float2*)&sAc[i*16+jr0];
    cd0+=(a.x!=0.f)?1.f:0.f; cd1+=(a.y!=0.f)?1.f:0.f;
  }
  cd0=wsum(cd0); cd1=wsum(cd1);
  if(hf==1){
    *(float4*)&sAg[jr0*132+c0]=A0;
    *(float4*)&sAg[jr1*132+c0]=A1;
  }
  if(lane==0){ sDeg[hf*16+jr0]=cd0; sDeg[hf*16+jr1]=cd1; }
  __syncthreads();
  if(hf==0){
    float4 P0=*(const float4*)&sAg[jr0*132+c0];
    float4 P1=*(const float4*)&sAg[jr1*132+c0];
    float id0=1.f/fmaxf(sDeg[jr0]+sDeg[16+jr0],1.f);
    float id1=1.f/fmaxf(sDeg[jr1]+sDeg[16+jr1],1.f);
    A0.x=(A0.x+P0.x)*id0;A0.y=(A0.y+P0.y)*id0;A0.z=(A0.z+P0.z)*id0;A0.w=(A0.w+P0.w)*id0;
    A1.x=(A1.x+P1.x)*id1;A1.y=(A1.y+P1.y)*id1;A1.z=(A1.z+P1.z)*id1;A1.w=(A1.w+P1.w)*id1;
    *(float4*)&sAg[jr0*132+c0]=A0;
    *(float4*)&sAg[jr1*132+c0]=A1;
  }
  __syncthreads();

  // dense: warps 0-7 agg@W1, warps 8-15 h@W2 (same row pair)
  float4 O0={0,0,0,0},O1={0,0,0,0};
  if(w<8){
    const float* g0=&sAg[jr0*132]; const float* g1=&sAg[jr1*132];
#pragma unroll 4
    for(int k=0;k<128;++k){
      float a0=g0[k],a1=g1[k];
      float4 wv=*(const float4*)&sW[k*128+c0];
      fma4(O0,a0,wv); fma4(O1,a1,wv);
    }
  }else{
    int ja=(jA<n)?jA:0,jb=(jB<n)?jB:0;
    const float* h0p=&sH[ja*128]; const float* h1p=&sH[jb*128];
#pragma unroll 4
    for(int k=0;k<128;++k){
      float h0=h0p[k],h1=h1p[k];
      float4 wv=*(const float4*)&sW[16384+k*128+c0];
      fma4(O0,h0,wv); fma4(O1,h1,wv);
    }
    *(float4*)&sAc[jr0*128+c0]=O0;
    *(float4*)&sAc[jr1*128+c0]=O1;
  }
  __syncthreads();
  if(w<8){
    float4 P0=*(const float4*)&sAc[jr0*128+c0];
    float4 P1=*(const float4*)&sAc[jr1*128+c0];
    float4 bb=__ldg((const float4*)(brel+c0));
    float4 V0,V1;
    V0.x=fmaxf(O0.x+P0.x+bb.x,0.f);V0.y=fmaxf(O0.y+P0.y+bb.y,0.f);
    V0.z=fmaxf(O0.z+P0.z+bb.z,0.f);V0.w=fmaxf(O0.w+P0.w+bb.w,0.f);
    V1.x=fmaxf(O1.x+P1.x+bb.x,0.f);V1.y=fmaxf(O1.y+P1.y+bb.y,0.f);
    V1.z=fmaxf(O1.z+P1.z+bb.z,0.f);V1.w=fmaxf(O1.w+P1.w+bb.w,0.f);
    if(jA<n) *(float4*)&hout[jA*128+c0]=V0; else V0=make_float4(0,0,0,0);
    if(jB<n) *(float4*)&hout[jB*128+c0]=V1; else V1=make_float4(0,0,0,0);
    float4 P; P.x=V0.x+V1.x;P.y=V0.y+V1.y;P.z=V0.z+V1.z;P.w=V0.w+V1.w;
    *(float4*)&sRed[p*128+c0]=P;
  }
  __syncthreads();
  if(tid<128){
    float s=0.f;
#pragma unroll
    for(int q=0;q<8;++q) s+=sRed[q*128+tid];
    atomicAdd(&g_xs[g*640+slot*128+tid],s*invn);
  }
}

// ---------------- fused poolq + softmax + x_new + fitness prep ----------------
__device__ void dv_pqsm(float* sm,int g,int r,int tid,const float* __restrict__ hg,
                        const float* __restrict__ wt,const float* __restrict__ linb,
                        const float* __restrict__ attw,const float* __restrict__ attbp,
                        const float* __restrict__ le1w,const float* __restrict__ le1bp,
                        const float* __restrict__ le2w,const float* __restrict__ le3w,int n){
  float* sH=sm+O_H; float* sW=sm+O_W; float* sAc=sm+O_AC; float* sAg=sm+O_AG; float* sax=sm+O_SA;
  int lane=tid&31,w=tid>>5,c0=lane*4;
  int p=w&7;
  int j0=r*16,jr0=2*p,jr1=jr0+1,jA=j0+jr0,jB=j0+jr1;
  const float* Ab=g_A+g*GS;

  for(int idx=tid;idx<16384;idx+=NT){
    int i=idx>>7;
    sH[idx]=(i<n)?__ldcg(hg+idx):0.f;
  }
  for(int idx=tid;idx<2048;idx+=NT){
    int i=idx>>4,jr=idx&15,j=j0+jr;
    sAc[idx]=(i<n&&j<n)?__ldcg(Ab+i*128+j):0.f;
  }
  for(int i4=tid;i4<4096;i4+=NT) ((float4*)sW)[i4]=__ldg((const float4*)wt+i4);
  __syncthreads();

  float aq0=0.f,aq1=0.f;
  if(w<8){
    // masked col max (diag implicit)
    float4 M0=make_float4(-1e30f,-1e30f,-1e30f,-1e30f),M1=M0;
    for(int i=0;i<n;++i){
      float2 av=*(const float2*)&sAc[i*16+jr0];
      bool m0=(av.x!=0.f)||(i==jA), m1=(av.y!=0.f)||(i==jB);
      if(m0||m1){
        float4 hv=*(const float4*)&sH[i*128+c0];
        if(m0){M0.x=fmaxf(M0.x,hv.x);M0.y=fmaxf(M0.y,hv.y);M0.z=fmaxf(M0.z,hv.z);M0.w=fmaxf(M0.w,hv.w);}
        if(m1){M1.x=fmaxf(M1.x,hv.x);M1.y=fmaxf(M1.y,hv.y);M1.z=fmaxf(M1.z,hv.z);M1.w=fmaxf(M1.w,hv.w);}
      }
    }
    *(float4*)&sAg[jr0*132+c0]=M0;
    *(float4*)&sAg[jr1*132+c0]=M1;
    __syncwarp();
    // q = maskedmax @ linw + linb ; aq = q . a_q
    const float* q0p=&sAg[jr0*132]; const float* q1p=&sAg[jr1*132];
    float4 Q0={0,0,0,0},Q1={0,0,0,0};
#pragma unroll 4
    for(int k=0;k<128;++k){
      float a0=q0p[k],a1=q1p[k];
      float4 wv=*(const float4*)&sW[k*128+c0];
      fma4(Q0,a0,wv); fma4(Q1,a1,wv);
    }
    float4 lb=__ldg((const float4*)(linb+c0));
    Q0.x+=lb.x;Q0.y+=lb.y;Q0.z+=lb.z;Q0.w+=lb.w;
    Q1.x+=lb.x;Q1.y+=lb.y;Q1.z+=lb.z;Q1.w+=lb.w;
    float4 awq=__ldg((const float4*)(attw+c0));
    aq0=wsum(dot4(Q0,awq));
    aq1=wsum(dot4(Q1,awq));
  }else{
    // ax[i] = h[i] . a_x for all rows (8 warps x 16 rows)
    float4 awx=__ldg((const float4*)(attw+128+c0));
    int base=(w-8)*16;
#pragma unroll
    for(int t=0;t<16;++t){
      int i=base+t;
      float4 hv=*(const float4*)&sH[i*128+c0];
      float d=wsum(dot4(hv,awx));
      if(lane==0) sax[i]=d;
    }
  }
  __syncthreads();

  if(w<8){
    float attb=__ldg(attbp);
    float q0=aq0+attb, q1=aq1+attb;
    float l0[4],l1[4]; int m0[4],m1[4];
    float mx0=-1e30f,mx1=-1e30f;
#pragma unroll
    for(int u=0;u<4;++u){
      int i=lane+32*u;
      float2 av=*(const float2*)&sAc[i*16+jr0];
      int b0=(i<n)&&(jA<n)&&((av.x!=0.f)||(i==jA));
      int b1=(i<n)&&(jB<n)&&((av.y!=0.f)||(i==jB));
      float ax=sax[i];
      float t0=ax+q0; t0=(t0>=0.f)?t0:0.2f*t0;
      float t1=ax+q1; t1=(t1>=0.f)?t1:0.2f*t1;
      l0[u]=b0?t0:-1e30f; m0[u]=b0; mx0=fmaxf(mx0,l0[u]);
      l1[u]=b1?t1:-1e30f; m1[u]=b1; mx1=fmaxf(mx1,l1[u]);
    }
    mx0=wmax(mx0); mx1=wmax(mx1);
    float Z0=0.f,Z1=0.f; float s0[4],s1[4];
#pragma unroll
    for(int u=0;u<4;++u){
      s0[u]=m0[u]?expf(l0[u]-mx0):0.f; Z0+=s0[u];
      s1[u]=m1[u]?expf(l1[u]-mx1):0.f; Z1+=s1[u];
    }
    Z0=wsum(Z0); Z1=wsum(Z1);
    float iz0=(jA<n)?1.f/Z0:0.f, iz1=(jB<n)?1.f/Z1:0.f;
#pragma unroll
    for(int u=0;u<4;++u){
      int i=lane+32*u;
      float v0=s0[u]*iz0, v1=s1[u]*iz1;
      sAg[jr0*132+i]=v0; sAg[jr1*132+i]=v1;
      if(i<n){
        if(jA<n) g_S[g*GS+i*128+jA]=v0;
        if(jB<n) g_S[g*GS+i*128+jB]=v1;
      }
    }
    __syncwarp();
    float4 O0={0,0,0,0},O1={0,0,0,0};
    for(int i=0;i<n;++i){
      float t0=sAg[jr0*132+i], t1=sAg[jr1*132+i];
      if(t0!=0.f||t1!=0.f){
        float4 hv=*(const float4*)&sH[i*128+c0];
        fma4(O0,t0,hv); fma4(O1,t1,hv);
      }
    }
    if(jA<n) *(float4*)&g_x2[g*GS+jA*128+c0]=O0;
    if(jB<n) *(float4*)&g_x2[g*GS+jB*128+c0]=O1;
    float4 w1v=__ldg((const float4*)(le1w+c0));
    float4 w2v=__ldg((const float4*)(le2w+c0));
    float4 w3v=__ldg((const float4*)(le3w+c0));
    float a0=wsum(dot4(O0,w1v)), b0=wsum(dot4(O0,w2v)), cc0=wsum(dot4(O0,w3v));
    float a1=wsum(dot4(O1,w1v)), b1=wsum(dot4(O1,w2v)), cc1=wsum(dot4(O1,w3v));
    if(lane==0){
      float l1b=__ldg(le1bp);
      if(jA<n){g_fa[g*128+jA]=a0+l1b; g_fb[g*128+jA]=b0; g_fc[g*128+jA]=cc0;}
      if(jB<n){g_fa[g*128+jB]=a1+l1b; g_fb[g*128+jB]=b1; g_fc[g*128+jB]=cc1;}
    }
  }
}

// ---------------- T = A_diag @ S  +  fitness finalize ----------------
__device__ void dv_fitT(float* sm,int g,int r,int tid,const float* __restrict__ le3bp,int n){
  float* sS=sm+O_H; float* sAr=sm+O_W; float* sAc=sm+O_AC; float* sa=sm+O_SA;
  int lane=tid&31,w=tid>>5,c0=lane*4;
  int p=w&7;
  int j0=r*16,jr0=2*p,jr1=jr0+1,jA=j0+jr0,jB=j0+jr1;
  const float* Ab=g_A+g*GS;
  for(int idx=tid;idx<16384;idx+=NT){
    int i=idx>>7;
    sS[idx]=(i<n)?__ldcg(g_S+g*GS+idx):0.f;
  }
  for(int idx=tid;idx<2048;idx+=NT){
    int it=idx>>7,m=idx&127,i=j0+it;
    float v=(i<n&&m<n)?__ldcg(Ab+i*128+m):0.f;
    if(m==i&&i<n) v=1.f;
    sAr[it*132+m]=v;
  }
  for(int idx=tid;idx<2048;idx+=NT){
    int i=idx>>4,jr=idx&15,j=j0+jr;
    sAc[idx]=(i<n&&j<n)?__ldcg(Ab+i*128+j):0.f;
  }
  if(tid<128) sa[tid]=(tid<n)?__ldcg(g_fa+g*128+tid):0.f;
  __syncthreads();
  if(w<8){
    const float* a0p=&sAr[jr0*132]; const float* a1p=&sAr[jr1*132];
    float4 T0={0,0,0,0},T1={0,0,0,0};
    for(int m=0;m<n;++m){
      float a0=a0p[m],a1=a1p[m];
      if(a0!=0.f||a1!=0.f){
        float4 sv=*(const float4*)&sS[m*128+c0];
        fma4(T0,a0,sv); fma4(T1,a1,sv);
      }
    }
    if(jA<n) *(float4*)&g_T[g*GS+jA*128+c0]=T0;
    if(jB<n) *(float4*)&g_T[g*GS+jB*128+c0]=T1;
    float s0=0.f,s1=0.f,d0=0.f,d1=0.f;
    for(int i=lane;i<n;i+=32){
      float2 av=*(const float2*)&sAc[i*16+jr0];
      if((av.x!=0.f)||(i==jA)){s0+=sa[i];d0+=1.f;}
      if((av.y!=0.f)||(i==jB)){s1+=sa[i];d1+=1.f;}
    }
    s0=wsum(s0);d0=wsum(d0);s1=wsum(s1);d1=wsum(d1);
    if(lane==0){
      float l3b=__ldg(le3bp);
      if(jA<n){
        float f=s0-d0*__ldcg(g_fb+g*128+jA)+__ldcg(g_fc+g*128+jA)+l3b;
        g_fit[g*128+jA]=1.f/(1.f+expf(-f));
      }
      if(jB<n){
        float f=s1-d1*__ldcg(g_fb+g*128+jB)+__ldcg(g_fc+g*128+jB)+l3b;
        g_fit[g*128+jB]=1.f/(1.f+expf(-f));
      }
    }
  }
}

// ---------------- B = S^T @ T  +  top-k ----------------
__device__ void dv_B(float* sm,int g,int r,int tid,int n,int k){
  float* sT=sm+O_H; float* sSc=sm+O_AC;
  int lane=tid&31,w=tid>>5,c0=lane*4;
  int p=w&7;
  int j0=r*16,jr0=2*p,jr1=jr0+1,jA=j0+jr0,jB=j0+jr1;
  for(int idx=tid;idx<16384;idx+=NT){
    int i=idx>>7;
    sT[idx]=(i<n)?__ldcg(g_T+g*GS+idx):0.f;
  }
  for(int idx=tid;idx<2048;idx+=NT){
    int i=idx>>4,jr=idx&15,j=j0+jr;
    sSc[idx]=(i<n&&j<n)?__ldcg(g_S+g*GS+i*128+j):0.f;
  }
  __syncthreads();
  if(w<8){
    float4 B0={0,0,0,0},B1={0,0,0,0};
    for(int i=0;i<n;++i){
      float2 sv=*(const float2*)&sSc[i*16+jr0];
      if(sv.x!=0.f||sv.y!=0.f){
        float4 tv=*(const float4*)&sT[i*128+c0];
        fma4(B0,sv.x,tv); fma4(B1,sv.y,tv);
      }
    }
    if(jA<n) *(float4*)&g_B[g*GS+jA*128+c0]=B0;
    if(jB<n) *(float4*)&g_B[g*GS+jB*128+c0]=B1;
  }
  if(r==0&&w==0){
    float v[4]; bool used[4];
#pragma unroll
    for(int u=0;u<4;++u){
      int jj=lane+32*u;
      v[u]=(jj<n)?__ldcg(g_fit+g*128+jj):-3.4e38f;
      used[u]=false;
    }
    for(int rr=0;rr<k;++rr){
      float bv=-3.4e38f; int bi=1<<30;
#pragma unroll
      for(int u=0;u<4;++u){
        if(!used[u]){
          int jj=lane+32*u;
          if(v[u]>bv||(v[u]==bv&&jj<bi)){bv=v[u];bi=jj;}
        }
      }
#pragma unroll
      for(int o=16;o;o>>=1){
        float ov=__shfl_xor_sync(FULL,bv,o);
        int oi=__shfl_xor_sync(FULL,bi,o);
        if(ov>bv||(ov==bv&&oi<bi)){bv=ov;bi=oi;}
      }
      if((bi&31)==lane) used[bi>>5]=true;
      if(lane==0) g_perm[g*128+rr]=bi;
    }
  }
}

// ---------------- gather: A2 + x_out ----------------
__device__ void dv_gather(float* sm,int g,int r,int tid,float* __restrict__ hout,int n,int k){
  int* sp=(int*)(sm+O_PERM);
  if(tid<128) sp[tid]=(tid<k)?__ldcg(g_perm+g*128+tid):0;
  __syncthreads();
  int i0=r*16;
  for(int idx=tid;idx<2048;idx+=NT){
    int rt=idx>>7,c=idx&127,rr=i0+rt;
    if(rr<k){
      int pj=sp[rr];
      float fv=__ldcg(g_fit+g*128+pj);
      float a2=0.f;
      if(c<k) a2=(c==rr)?1.f:__ldcg(g_B+g*GS+pj*128+sp[c]);
      g_A[g*GS+rr*128+c]=a2;
      hout[rr*128+c]=__ldcg(g_x2+g*GS+pj*128+c)*fv;
    }
  }
}

// ---------------- head ----------------
__device__ void dv_head(float* sm,int g,int tid,const float* __restrict__ b1,
                        const float* __restrict__ w2,const float* __restrict__ b2,
                        float* __restrict__ out){
  float* sJ=sm+O_H; float* z1=sm+O_H+704; float* z2=sm+O_H+840;
  for(int c=tid;c<640;c+=NT) sJ[c]=__ldcg(g_xs+g*640+c);
  __syncthreads();
  if(tid<128){
    float s=__ldg(b1+tid);
    for(int c=0;c<640;++c) s=fmaf(sJ[c],g_w1t[c*128+tid],s);
    z1[tid]=fmaxf(s,0.f);
  }
  __syncthreads();
  if(tid<2){
    float s2=__ldg(b2+tid);
    for(int c=0;c<128;++c) s2=fmaf(z1[c],__ldg(w2+tid*128+c),s2);
    z2[tid]=s2;
  }
  __syncthreads();
  if(tid==0){
    float m=fmaxf(z2[0],z2[1]);
    float lse=m+logf(expf(z2[0]-m)+expf(z2[1]-m));
    out[g*2+0]=z2[0]-lse;
    out[g*2+1]=z2[1]-lse;
  }
}

// ---------------- fused kernel ----------------
__global__ void __launch_bounds__(NT,1)
k_fused(const float* __restrict__ x,const int* __restrict__ ei,int E,
        const float* __restrict__ c0_brel,const float* __restrict__ cb_rel,
        const float* __restrict__ p_lin_b,const float* __restrict__ p_att_w,
        const float* __restrict__ p_att_b,
        const float* __restrict__ p_le1_w,const float* __restrict__ p_le1_b,
        const float* __restrict__ p_le2_w,const float* __restrict__ p_le3_w,
        const float* __restrict__ p_le3_b,
        const float* __restrict__ lin1_b,const float* __restrict__ lin2_w,
        const float* __restrict__ lin2_b,float* __restrict__ out){
  extern __shared__ float sm[];
  int g=blockIdx.x>>3,r=blockIdx.x&7,tid=threadIdx.x;
  float* hA=g_h+g*GS;
  float* hB=g_hb+g*GS;
  int sl=0;
  int j0=r*16;
  for(int idx=tid;idx<2048;idx+=NT) g_A[g*GS+(j0+(idx>>7))*128+(idx&127)]=0.f;
  if(r==0) for(int i=tid;i<640;i+=NT) g_xs[g*640+i]=0.f;
  __syncthreads();
  if(tid<256){
    int e=(g*128+j0)*16+tid;
    int u=__ldg(ei+e),v=__ldg(ei+E+e);
    g_A[g*GS+(u&127)*128+(v&127)]=1.f;
  }
  gbar(g,sl++,tid);

  dv_conv(sm,g,r,tid,x+g*128*64,64,hA,g_wt+0*GS,g_wt+1*GS,c0_brel,0,128,1.f/128.f);
  gbar(g,sl++,tid);
  dv_conv(sm,g,r,tid,hA,128,hB,g_wt+2*GS,g_wt+6*GS,cb_rel+0,1,128,1.f/128.f);
  gbar(g,sl++,tid);

  // pool 1: 128 -> 103, h=hB, x_out -> hA
  dv_pqsm(sm,g,r,tid,hB,g_wt+10*GS,p_lin_b+0,p_att_w+0,p_att_b+0,
          p_le1_w+0,p_le1_b+0,p_le2_w+0,p_le3_w+0,128);
  gbar(g,sl++,tid);
  dv_fitT(sm,g,r,tid,p_le3_b+0,128);
  gbar(g,sl++,tid);
  dv_B(sm,g,r,tid,128,103);
  gbar(g,sl++,tid);
  dv_gather(sm,g,r,tid,hA,128,103);
  gbar(g,sl++,tid);

  dv_conv(sm,g,r,tid,hA,128,hB,g_wt+3*GS,g_wt+7*GS,cb_rel+128,2,103,1.f/103.f);
  gbar(g,sl++,tid);
  dv_conv(sm,g,r,tid,hB,128,hA,g_wt+4*GS,g_wt+8*GS,cb_rel+256,3,103,1.f/103.f);
  gbar(g,sl++,tid);

  // pool 2: 103 -> 83, h=hA, x_out -> hB
  dv_pqsm(sm,g,r,tid,hA,g_wt+11*GS,p_lin_b+128,p_att_w+256,p_att_b+1,
          p_le1_w+128,p_le1_b+1,p_le2_w+128,p_le3_w+128,103);
  gbar(g,sl++,tid);
  dv_fitT(sm,g,r,tid,p_le3_b+1,103);
  gbar(g,sl++,tid);
  dv_B(sm,g,r,tid,103,83);
  gbar(g,sl++,tid);
  dv_gather(sm,g,r,tid,hB,103,83);
  gbar(g,sl++,tid);

  dv_conv(sm,g,r,tid,hB,128,hA,g_wt+5*GS,g_wt+9*GS,cb_rel+384,4,83,1.f/83.f);
  gbar(g,sl++,tid);

  if(r==0) dv_head(sm,g,tid,lin1_b,lin2_w,lin2_b,out);
}

// ---------------- host ----------------
extern "C" void kernel_launch(void* const* d_in,const int* in_sizes,int n_in,
                              void* d_out,int out_size){
  const float* x       =(const float*)d_in[0];
  const int*   ei      =(const int*)  d_in[1];
  const float* c0_wrel =(const float*)d_in[2];
  const float* c0_brel =(const float*)d_in[3];
  const float* c0_wroot=(const float*)d_in[4];
  const float* cw_rel  =(const float*)d_in[5];
  const float* cb_rel  =(const float*)d_in[6];
  const float* cw_root =(const float*)d_in[7];
  const float* p_lin_w =(const float*)d_in[8];
  const float* p_lin_b =(const float*)d_in[9];
  const float* p_att_w =(const float*)d_in[10];
  const float* p_att_b =(const float*)d_in[11];
  const float* p_le1_w =(const float*)d_in[12];
  const float* p_le1_b =(const float*)d_in[13];
  const float* p_le2_w =(const float*)d_in[14];
  const float* p_le3_w =(const float*)d_in[15];
  const float* p_le3_b =(const float*)d_in[16];
  const float* lin1_w  =(const float*)d_in[17];
  const float* lin1_b  =(const float*)d_in[18];
  const float* lin2_w  =(const float*)d_in[19];
  const float* lin2_b  =(const float*)d_in[20];

  static int inited=0;
  const size_t SMB=(size_t)SMF*4;
  if(!inited){
    cudaFuncSetAttribute(k_fused,cudaFuncAttributeMaxDynamicSharedMemorySize,(int)SMB);
    inited=1;
  }
  int E=in_sizes[1]/2;
  k_prep<<<1090,256>>>(c0_wrel,c0_wroot,cw_rel,cw_root,p_lin_w,lin1_w);
  k_fused<<<NG*NCTA,NT,SMB>>>(x,ei,E,c0_brel,cb_rel,
                              p_lin_b,p_att_w,p_att_b,
                              p_le1_w,p_le1_b,p_le2_w,p_le3_w,p_le3_b,
                              lin1_b,lin2_w,lin2_b,(float*)d_out);
}